// round 6
// baseline (speedup 1.0000x reference)
#include <cuda_runtime.h>
#include <cooperative_groups.h>
#include <cstdint>
namespace cg = cooperative_groups;

// ------------------------- scratch (device globals) -------------------------
#define BT (256*512)
__device__ float g_x64 [256*64];
__device__ float g_xg1f[(size_t)BT*512];
__device__ float g_xg1b[(size_t)BT*512];
__device__ float g_Y   [(size_t)BT*256];   // lstm1 output, fp32
__device__ float g_xg2f[(size_t)BT*256];
__device__ float g_xg2b[(size_t)BT*256];
__device__ float g_h2  [256*128];
__device__ float g_wT  [4*65536];          // transposed weights [N,K], fp32

// ------------------------- small PTX helpers --------------------------------
__device__ __forceinline__ uint32_t smem_u32(const void* p) {
    uint32_t a;
    asm("{ .reg .u64 t; cvta.to.shared.u64 t, %1; cvt.u32.u64 %0, t; }" : "=r"(a) : "l"(p));
    return a;
}
__device__ __forceinline__ uint32_t f2tf32(float v) {
    uint32_t r;
    asm("cvt.rna.tf32.f32 %0, %1;" : "=r"(r) : "f"(v));
    return r;
}
// split fp32 -> tf32 hi + tf32 lo (hi+lo ~= full fp32 precision)
__device__ __forceinline__ void tf32_split(uint32_t v, uint32_t& hi, uint32_t& lo) {
    float f = __uint_as_float(v);
    hi = f2tf32(f);
    lo = f2tf32(f - __uint_as_float(hi));
}
__device__ __forceinline__ void mma_tf32(float* c, const uint32_t* a, const uint32_t* b) {
    asm volatile("mma.sync.aligned.m16n8k8.row.col.f32.tf32.tf32.f32 "
        "{%0,%1,%2,%3},{%4,%5,%6,%7},{%8,%9},{%0,%1,%2,%3};"
        : "+f"(c[0]), "+f"(c[1]), "+f"(c[2]), "+f"(c[3])
        : "r"(a[0]), "r"(a[1]), "r"(a[2]), "r"(a[3]), "r"(b[0]), "r"(b[1]));
}
#define LDMATRIX_X4(r0, r1, r2, r3, addr) \
    asm volatile("ldmatrix.sync.aligned.m8n8.x4.shared.b16 {%0,%1,%2,%3}, [%4];" \
        : "=r"(r0), "=r"(r1), "=r"(r2), "=r"(r3) : "r"(addr))
#define CP_ASYNC16(dst, src) asm volatile("cp.async.cg.shared.global [%0], [%1], 16;" :: "r"(dst), "l"(src))
#define CP_COMMIT()          asm volatile("cp.async.commit_group;" ::: "memory")
#define CP_WAIT(n)           asm volatile("cp.async.wait_group %0;" :: "n"(n) : "memory")

__device__ __forceinline__ float sigf(float x) {
    return 1.f / (1.f + __expf(-x));
}

// ------------------- prep: weight transpose (fp32, no rounding) -------------
__global__ void __launch_bounds__(256)
transpose_kernel(const float* __restrict__ in, float* __restrict__ out, int K, int N)
{
    int idx = blockIdx.x * 256 + threadIdx.x;
    if (idx < K * N) {
        int n = idx / K, k = idx - n * K;
        out[idx] = in[k * N + n];
    }
}

// ---- near-fp32 GEMM + bias via 3-product split-tf32 mma -------------------
// C[M,N] = A[M,K] @ Wt[N,K]^T + b. Block 128x128, BK=32, 2-stage cp.async,
// 8 warps (2m x 4n), warp tile 64x32, ldmatrix fragments, hi/lo split per frag.
#define STAGE_BYTES 36864
__global__ void __launch_bounds__(256, 2)
gemm_mma_kernel(const float* __restrict__ A, const float* __restrict__ Wt,
                const float* __restrict__ bias, float* __restrict__ C,
                int M, int N, int K)
{
    extern __shared__ char smem[];
    const uint32_t smem_base = smem_u32(smem);
    const int tid = threadIdx.x;
    const int lane = tid & 31, wid = tid >> 5;
    const int m0 = blockIdx.x * 128, n0 = blockIdx.y * 128;
    const int wm = (wid >> 2) * 64, wn = (wid & 3) * 32;

    float acc[4][4][4];
    #pragma unroll
    for (int mt = 0; mt < 4; ++mt)
        #pragma unroll
        for (int nt = 0; nt < 4; ++nt)
            #pragma unroll
            for (int q = 0; q < 4; ++q) acc[mt][nt][q] = 0.f;

    const int rowsel = ((lane & 16) >> 1) + (lane & 7);
    const int colsel = ((lane >> 3) & 1) * 4;
    uint32_t offA[4], offB[2];
    #pragma unroll
    for (int mt = 0; mt < 4; ++mt)
        offA[mt] = (uint32_t)(((wm + mt * 16 + rowsel) * 36 + colsel) * 4);
    #pragma unroll
    for (int p = 0; p < 2; ++p)
        offB[p] = 18432u + (uint32_t)(((wn + p * 16 + rowsel) * 36 + colsel) * 4);

    const int nch = K >> 5;
    auto issue = [&](int ch, int stage) {
        const int kc = ch << 5;
        const uint32_t sA = smem_base + stage * STAGE_BYTES;
        const uint32_t sB = sA + 18432u;
        #pragma unroll
        for (int i = 0; i < 4; ++i) {
            int idx = tid + i * 256;
            int row = idx >> 3, c4 = idx & 7;
            CP_ASYNC16(sA + row * 144 + c4 * 16,
                       A + (size_t)(m0 + row) * K + kc + c4 * 4);
        }
        #pragma unroll
        for (int i = 0; i < 4; ++i) {
            int idx = tid + i * 256;
            int row = idx >> 3, c4 = idx & 7;
            CP_ASYNC16(sB + row * 144 + c4 * 16,
                       Wt + (size_t)(n0 + row) * K + kc + c4 * 4);
        }
        CP_COMMIT();
    };

    issue(0, 0);
    for (int ch = 0; ch < nch; ++ch) {
        if (ch + 1 < nch) { issue(ch + 1, (ch + 1) & 1); CP_WAIT(1); }
        else             { CP_WAIT(0); }
        __syncthreads();

        const uint32_t stg = smem_base + (ch & 1) * STAGE_BYTES;
        #pragma unroll
        for (int k8 = 0; k8 < 4; ++k8) {
            const uint32_t kb = (uint32_t)(k8 * 8 * 4);
            uint32_t braw[4][2], bhi[4][2], blo[4][2];
            #pragma unroll
            for (int p = 0; p < 2; ++p)
                LDMATRIX_X4(braw[2*p][0], braw[2*p][1], braw[2*p+1][0], braw[2*p+1][1],
                            stg + offB[p] + kb);
            #pragma unroll
            for (int nt = 0; nt < 4; ++nt)
                #pragma unroll
                for (int q = 0; q < 2; ++q)
                    tf32_split(braw[nt][q], bhi[nt][q], blo[nt][q]);

            #pragma unroll
            for (int mt = 0; mt < 4; ++mt) {
                uint32_t araw[4], ahi[4], alo[4];
                LDMATRIX_X4(araw[0], araw[2], araw[1], araw[3], stg + offA[mt] + kb);
                #pragma unroll
                for (int q = 0; q < 4; ++q) tf32_split(araw[q], ahi[q], alo[q]);
                #pragma unroll
                for (int nt = 0; nt < 4; ++nt) {
                    mma_tf32(acc[mt][nt], ahi, bhi[nt]);
                    mma_tf32(acc[mt][nt], ahi, blo[nt]);
                    mma_tf32(acc[mt][nt], alo, bhi[nt]);
                }
            }
        }
        __syncthreads();
    }

    #pragma unroll
    for (int mt = 0; mt < 4; ++mt) {
        int r = m0 + wm + mt * 16 + (lane >> 2);
        #pragma unroll
        for (int nt = 0; nt < 4; ++nt) {
            int col = n0 + wn + nt * 8 + (lane & 3) * 2;
            float b0 = __ldg(bias + col), b1 = __ldg(bias + col + 1);
            float2 v0 = make_float2(acc[mt][nt][0] + b0, acc[mt][nt][1] + b1);
            float2 v1 = make_float2(acc[mt][nt][2] + b0, acc[mt][nt][3] + b1);
            *(float2*)(C + (size_t)r * N + col)       = v0;
            *(float2*)(C + (size_t)(r + 8) * N + col) = v1;
        }
    }
}

// ------------------------- embedding MLP branch -----------------------------
__global__ void __launch_bounds__(256)
emb_mlp_kernel(const int* __restrict__ inputA, const float* __restrict__ emb,
               const float* __restrict__ w1, const float* __restrict__ b1,
               const float* __restrict__ w2, const float* __restrict__ b2,
               const float* __restrict__ w3, const float* __restrict__ b3,
               float* __restrict__ xout)
{
    __shared__ float x0[600], x1[256], x2[128];
    const int b = blockIdx.x, tid = threadIdx.x;
    for (int i = tid; i < 600; i += 256) {
        int la = i / 3, comp = i - la * 3;
        x0[i] = emb[inputA[b*200 + la]*3 + comp];
    }
    __syncthreads();
    {
        float acc = b1[tid];
        #pragma unroll 4
        for (int k = 0; k < 600; ++k) acc += x0[k] * w1[k*256 + tid];
        x1[tid] = fmaxf(acc, 0.f);
    }
    __syncthreads();
    if (tid < 128) {
        float acc = b2[tid];
        #pragma unroll 4
        for (int k = 0; k < 256; ++k) acc += x1[k] * w2[k*128 + tid];
        x2[tid] = fmaxf(acc, 0.f);
    }
    __syncthreads();
    if (tid < 64) {
        float acc = b3[tid];
        #pragma unroll 4
        for (int k = 0; k < 128; ++k) acc += x2[k] * w3[k*64 + tid];
        xout[b*64 + tid] = fmaxf(acc, 0.f);
    }
}

// ------------- LSTM layer 1 (H=128) — tensor-core recurrence ----------------
// 2-CTA cluster; rank owns 64 h-indices (256 gate cols, interleaved i,f,c,o).
// Weights: register-resident tf32 B-fragments (loaded once).
// Per step: xg -> acc, 16x ldmatrix(h) + 64 HMMA per warp, shuffle-combine
// activations, h -> own+peer smem (tf32) + Y (fp32), cluster.sync.
__global__ void __cluster_dims__(2,1,1) __launch_bounds__(256, 1)
lstm1_mma_kernel(const float* __restrict__ xg1f, const float* __restrict__ xg1b,
                 const float* __restrict__ r1f,  const float* __restrict__ r1b,
                 float* __restrict__ Y)
{
    __shared__ float hbuf[2 * 16 * 132];

    cg::cluster_group cl = cg::this_cluster();
    const int rank = cl.block_rank();
    const int dir  = blockIdx.y;
    const int b0   = (blockIdx.x >> 1) * 16;
    const int tid  = threadIdx.x;
    const int lane = tid & 31, w = tid >> 5;
    const int q    = lane & 3;
    const float* xg = dir ? xg1b : xg1f;
    const float* Wr = dir ? r1b : r1f;

    // ---- load weight fragments into registers (once) ----
    // b[nt][kt][p]: element = tf32(Wr[k][G]), k = kt*8 + q + p*4,
    // G = g*128 + rank*64 + a, with n_local = w*32 + nt*8 + (lane>>2),
    // a = n_local>>2, g = n_local&3.
    uint32_t bfr[4][16][2];
    #pragma unroll
    for (int nt = 0; nt < 4; ++nt) {
        int n_local = w * 32 + nt * 8 + (lane >> 2);
        int G = (n_local & 3) * 128 + rank * 64 + (n_local >> 2);
        #pragma unroll
        for (int kt = 0; kt < 16; ++kt) {
            #pragma unroll
            for (int p = 0; p < 2; ++p) {
                int k = kt * 8 + q + p * 4;
                bfr[nt][kt][p] = f2tf32(Wr[k * 512 + G]);
            }
        }
    }

    // zero h buffers
    for (int i = tid; i < 2 * 16 * 132; i += 256) hbuf[i] = 0.f;

    // per-thread constants
    const int rowsel = ((lane & 16) >> 1) + (lane & 7);
    const int colsel = ((lane >> 3) & 1) * 4;
    const uint32_t hbase = smem_u32(hbuf);
    const bool isState = (lane & 1);                    // odd lanes hold (cc,o) + cell state
    const int g0 = (q & 1) * 2;                         // gate of acc col 0
    int colA[4], hj[4];
    #pragma unroll
    for (int nt = 0; nt < 4; ++nt) {
        int a_local = w * 8 + nt * 2 + (q >> 1);
        colA[nt] = g0 * 128 + rank * 64 + a_local;      // xg col of acc c0 (c1 = +128)
        hj[nt]   = rank * 64 + a_local;                 // global h index (for stores)
    }
    const int r = lane >> 2;                            // batch rows r, r+8

    float cst[4][2];
    #pragma unroll
    for (int nt = 0; nt < 4; ++nt) { cst[nt][0] = 0.f; cst[nt][1] = 0.f; }

    float* peer_h = cl.map_shared_rank(hbuf, rank ^ 1);
    __syncthreads();
    cl.sync();

    for (int t = 0; t < 512; ++t) {
        const int tt  = dir ? (511 - t) : t;
        const int cur = t & 1, nxt = cur ^ 1;

        // acc init = xg (gates = xg + h @ Wr)
        float acc[4][4];
        {
            size_t rowL = ((size_t)(b0 + r) * 512 + tt) * 512;
            size_t rowH = ((size_t)(b0 + r + 8) * 512 + tt) * 512;
            #pragma unroll
            for (int nt = 0; nt < 4; ++nt) {
                acc[nt][0] = __ldg(xg + rowL + colA[nt]);
                acc[nt][1] = __ldg(xg + rowL + colA[nt] + 128);
                acc[nt][2] = __ldg(xg + rowH + colA[nt]);
                acc[nt][3] = __ldg(xg + rowH + colA[nt] + 128);
            }
        }

        // h @ Wr via mma, A fragments from hbuf[cur]
        const uint32_t abase = hbase + (uint32_t)(cur * 16 * 132 * 4);
        #pragma unroll
        for (int kt = 0; kt < 16; ++kt) {
            uint32_t a0, a1, a2, a3;
            uint32_t addr = abase + (uint32_t)((rowsel * 132 + kt * 8 + colsel) * 4);
            LDMATRIX_X4(a0, a2, a1, a3, addr);
            uint32_t afr[4] = {a0, a1, a2, a3};
            #pragma unroll
            for (int nt = 0; nt < 4; ++nt)
                mma_tf32(acc[nt], afr, bfr[nt][kt]);
        }

        // activations + state update + h write
        #pragma unroll
        for (int nt = 0; nt < 4; ++nt) {
            float v0 = isState ? fmaxf(acc[nt][0], 0.f) : sigf(acc[nt][0]);
            float v1 = sigf(acc[nt][1]);
            float v2 = isState ? fmaxf(acc[nt][2], 0.f) : sigf(acc[nt][2]);
            float v3 = sigf(acc[nt][3]);
            float s0 = __shfl_xor_sync(0xffffffffu, v0, 1);  // sig(i)
            float s1 = __shfl_xor_sync(0xffffffffu, v1, 1);  // sig(f)
            float s2 = __shfl_xor_sync(0xffffffffu, v2, 1);
            float s3 = __shfl_xor_sync(0xffffffffu, v3, 1);
            if (isState) {
                float c0 = s1 * cst[nt][0] + s0 * v0;
                float c1 = s3 * cst[nt][1] + s2 * v2;
                cst[nt][0] = c0; cst[nt][1] = c1;
                float h0 = v1 * fmaxf(c0, 0.f);
                float h1 = v3 * fmaxf(c1, 0.f);
                float h0r = __uint_as_float(f2tf32(h0));
                float h1r = __uint_as_float(f2tf32(h1));
                int o0 = nxt * 16 * 132 + r * 132 + hj[nt];
                int o1 = nxt * 16 * 132 + (r + 8) * 132 + hj[nt];
                hbuf[o0] = h0r;  hbuf[o1] = h1r;
                peer_h[o0] = h0r; peer_h[o1] = h1r;
                Y[((size_t)(b0 + r) * 512 + tt) * 256 + dir * 128 + hj[nt]]     = h0;
                Y[((size_t)(b0 + r + 8) * 512 + tt) * 256 + dir * 128 + hj[nt]] = h1;
            }
        }
        cl.sync();
    }
}

// ------------- LSTM layer 2 (H=64) — tensor-core recurrence -----------------
// Single CTA covers all 256 gate cols; same interleaved layout, no cluster.
__global__ void __launch_bounds__(256, 1)
lstm2_mma_kernel(const float* __restrict__ xg2f, const float* __restrict__ xg2b,
                 const float* __restrict__ r2f,  const float* __restrict__ r2b,
                 float* __restrict__ hout)
{
    __shared__ float hbuf[2 * 16 * 68];

    const int dir = blockIdx.y;
    const int b0  = blockIdx.x * 16;
    const int tid = threadIdx.x;
    const int lane = tid & 31, w = tid >> 5;
    const int q = lane & 3;
    const float* xg = dir ? xg2b : xg2f;
    const float* Wr = dir ? r2b : r2f;

    uint32_t bfr[4][8][2];
    #pragma unroll
    for (int nt = 0; nt < 4; ++nt) {
        int n_local = w * 32 + nt * 8 + (lane >> 2);
        int G = (n_local & 3) * 64 + (n_local >> 2);
        #pragma unroll
        for (int kt = 0; kt < 8; ++kt) {
            #pragma unroll
            for (int p = 0; p < 2; ++p) {
                int k = kt * 8 + q + p * 4;
                bfr[nt][kt][p] = f2tf32(Wr[k * 256 + G]);
            }
        }
    }

    for (int i = tid; i < 2 * 16 * 68; i += 256) hbuf[i] = 0.f;

    const int rowsel = ((lane & 16) >> 1) + (lane & 7);
    const int colsel = ((lane >> 3) & 1) * 4;
    const uint32_t hbase = smem_u32(hbuf);
    const bool isState = (lane & 1);
    const int g0 = (q & 1) * 2;
    int colA[4], hj[4];
    #pragma unroll
    for (int nt = 0; nt < 4; ++nt) {
        int a_local = w * 8 + nt * 2 + (q >> 1);
        colA[nt] = g0 * 64 + a_local;
        hj[nt]   = a_local;
    }
    const int r = lane >> 2;

    float cst[4][2];
    #pragma unroll
    for (int nt = 0; nt < 4; ++nt) { cst[nt][0] = 0.f; cst[nt][1] = 0.f; }
    __syncthreads();

    for (int t = 0; t < 512; ++t) {
        const int tt  = dir ? (511 - t) : t;
        const int cur = t & 1, nxt = cur ^ 1;

        float acc[4][4];
        {
            size_t rowL = ((size_t)(b0 + r) * 512 + tt) * 256;
            size_t rowH = ((size_t)(b0 + r + 8) * 512 + tt) * 256;
            #pragma unroll
            for (int nt = 0; nt < 4; ++nt) {
                acc[nt][0] = __ldg(xg + rowL + colA[nt]);
                acc[nt][1] = __ldg(xg + rowL + colA[nt] + 64);
                acc[nt][2] = __ldg(xg + rowH + colA[nt]);
                acc[nt][3] = __ldg(xg + rowH + colA[nt] + 64);
            }
        }

        const uint32_t abase = hbase + (uint32_t)(cur * 16 * 68 * 4);
        #pragma unroll
        for (int kt = 0; kt < 8; ++kt) {
            uint32_t a0, a1, a2, a3;
            uint32_t addr = abase + (uint32_t)((rowsel * 68 + kt * 8 + colsel) * 4);
            LDMATRIX_X4(a0, a2, a1, a3, addr);
            uint32_t afr[4] = {a0, a1, a2, a3};
            #pragma unroll
            for (int nt = 0; nt < 4; ++nt)
                mma_tf32(acc[nt], afr, bfr[nt][kt]);
        }

        #pragma unroll
        for (int nt = 0; nt < 4; ++nt) {
            float v0 = isState ? fmaxf(acc[nt][0], 0.f) : sigf(acc[nt][0]);
            float v1 = sigf(acc[nt][1]);
            float v2 = isState ? fmaxf(acc[nt][2], 0.f) : sigf(acc[nt][2]);
            float v3 = sigf(acc[nt][3]);
            float s0 = __shfl_xor_sync(0xffffffffu, v0, 1);
            float s1 = __shfl_xor_sync(0xffffffffu, v1, 1);
            float s2 = __shfl_xor_sync(0xffffffffu, v2, 1);
            float s3 = __shfl_xor_sync(0xffffffffu, v3, 1);
            if (isState) {
                float c0 = s1 * cst[nt][0] + s0 * v0;
                float c1 = s3 * cst[nt][1] + s2 * v2;
                cst[nt][0] = c0; cst[nt][1] = c1;
                float h0 = v1 * fmaxf(c0, 0.f);
                float h1 = v3 * fmaxf(c1, 0.f);
                hbuf[nxt * 16 * 68 + r * 68 + hj[nt]]       = __uint_as_float(f2tf32(h0));
                hbuf[nxt * 16 * 68 + (r + 8) * 68 + hj[nt]] = __uint_as_float(f2tf32(h1));
                if (t == 511) {
                    hout[(size_t)(b0 + r) * 128 + dir * 64 + hj[nt]]     = h0;
                    hout[(size_t)(b0 + r + 8) * 128 + dir * 64 + hj[nt]] = h1;
                }
            }
        }
        __syncthreads();
    }
}

// ------------------------------ heads ---------------------------------------
__global__ void __launch_bounds__(256)
head_kernel(const float* __restrict__ x64, const float* __restrict__ h2,
            const float* __restrict__ wz1, const float* __restrict__ bz1,
            const float* __restrict__ wz2, const float* __restrict__ bz2,
            const float* __restrict__ wt1, const float* __restrict__ bt1,
            const float* __restrict__ wt2, const float* __restrict__ bt2,
            float* __restrict__ out)
{
    const int b = threadIdx.x;
    float comb[192];
    #pragma unroll 4
    for (int k = 0; k < 64; ++k)  comb[k]      = x64[b*64 + k];
    #pragma unroll 4
    for (int k = 0; k < 128; ++k) comb[64 + k] = h2[b*128 + k];

    float z0 = bz1[0], z1 = bz1[1], t0 = bt1[0], t1 = bt1[1];
    #pragma unroll 4
    for (int k = 0; k < 192; ++k) {
        float v = comb[k];
        z0 += v * wz1[k*2 + 0]; z1 += v * wz1[k*2 + 1];
        t0 += v * wt1[k*2 + 0]; t1 += v * wt1[k*2 + 1];
    }
    out[b]       = fmaxf(z0,0.f)*wz2[0] + fmaxf(z1,0.f)*wz2[1] + bz2[0];
    out[256 + b] = fmaxf(t0,0.f)*wt2[0] + fmaxf(t1,0.f)*wt2[1] + bt2[0];
}

// ------------------------------ launcher ------------------------------------
extern "C" void kernel_launch(void* const* d_in, const int* in_sizes, int n_in,
                              void* d_out, int out_size)
{
    const int*   inputA = (const int*)  d_in[0];
    const float* inputB = (const float*)d_in[1];
    const float* emb = (const float*)d_in[2];
    const float *w1=(const float*)d_in[3],  *b1=(const float*)d_in[4];
    const float *w2=(const float*)d_in[5],  *b2=(const float*)d_in[6];
    const float *w3=(const float*)d_in[7],  *b3=(const float*)d_in[8];
    const float *k1f=(const float*)d_in[9],  *r1f=(const float*)d_in[10], *bb1f=(const float*)d_in[11];
    const float *k1b=(const float*)d_in[12], *r1b=(const float*)d_in[13], *bb1b=(const float*)d_in[14];
    const float *k2f=(const float*)d_in[15], *r2f=(const float*)d_in[16], *bb2f=(const float*)d_in[17];
    const float *k2b=(const float*)d_in[18], *r2b=(const float*)d_in[19], *bb2b=(const float*)d_in[20];
    const float *wz1=(const float*)d_in[21], *bz1=(const float*)d_in[22];
    const float *wz2=(const float*)d_in[23], *bz2=(const float*)d_in[24];
    const float *wt1=(const float*)d_in[25], *bt1=(const float*)d_in[26];
    const float *wt2=(const float*)d_in[27], *bt2=(const float*)d_in[28];
    float* out = (float*)d_out;

    float *xg1f, *xg1b, *Y, *xg2f, *xg2b, *x64, *h2, *wT;
    cudaGetSymbolAddress((void**)&xg1f, g_xg1f);
    cudaGetSymbolAddress((void**)&xg1b, g_xg1b);
    cudaGetSymbolAddress((void**)&Y,    g_Y);
    cudaGetSymbolAddress((void**)&xg2f, g_xg2f);
    cudaGetSymbolAddress((void**)&xg2b, g_xg2b);
    cudaGetSymbolAddress((void**)&x64,  g_x64);
    cudaGetSymbolAddress((void**)&h2,   g_h2);
    cudaGetSymbolAddress((void**)&wT,   g_wT);
    float* wt1f = wT;
    float* wt1b = wT + 65536;
    float* wt2f = wT + 2*65536;
    float* wt2b = wT + 3*65536;

    static bool attr_done = false;
    if (!attr_done) {
        cudaFuncSetAttribute(gemm_mma_kernel, cudaFuncAttributeMaxDynamicSharedMemorySize, 2*STAGE_BYTES);
        attr_done = true;
    }

    transpose_kernel<<<(65536+255)/256, 256>>>(k1f, wt1f, 128, 512);
    transpose_kernel<<<(65536+255)/256, 256>>>(k1b, wt1b, 128, 512);
    transpose_kernel<<<(65536+255)/256, 256>>>(k2f, wt2f, 256, 256);
    transpose_kernel<<<(65536+255)/256, 256>>>(k2b, wt2b, 256, 256);

    emb_mlp_kernel<<<256, 256>>>(inputA, emb, w1,b1, w2,b2, w3,b3, x64);

    const size_t gsm = 2*STAGE_BYTES;
    gemm_mma_kernel<<<dim3(1024,4), 256, gsm>>>(inputB, wt1f, bb1f, xg1f, BT, 512, 128);
    gemm_mma_kernel<<<dim3(1024,4), 256, gsm>>>(inputB, wt1b, bb1b, xg1b, BT, 512, 128);

    lstm1_mma_kernel<<<dim3(32,2), 256>>>(xg1f, xg1b, r1f, r1b, Y);

    gemm_mma_kernel<<<dim3(1024,2), 256, gsm>>>(Y, wt2f, bb2f, xg2f, BT, 256, 256);
    gemm_mma_kernel<<<dim3(1024,2), 256, gsm>>>(Y, wt2b, bb2b, xg2b, BT, 256, 256);

    lstm2_mma_kernel<<<dim3(16,2), 256>>>(xg2f, xg2b, r2f, r2b, h2);

    head_kernel<<<1, 256>>>(x64, h2, wz1,bz1, wz2,bz2, wt1,bt1, wt2,bt2, out);
}

// round 8
// speedup vs baseline: 1.2700x; 1.2700x over previous
#include <cuda_runtime.h>
#include <cooperative_groups.h>
#include <cstdint>
namespace cg = cooperative_groups;

// ------------------------- scratch (device globals) -------------------------
#define BT (256*512)
__device__ float g_x64 [256*64];
__device__ float g_xg1f[(size_t)BT*512];
__device__ float g_xg1b[(size_t)BT*512];
__device__ float g_Y   [(size_t)BT*256];   // lstm1 output, fp32
__device__ float g_xg2f[(size_t)BT*256];
__device__ float g_xg2b[(size_t)BT*256];
__device__ float g_h2  [256*128];
__device__ float g_wT  [4*65536];          // transposed weights [N,K], fp32

// ------------------------- small PTX helpers --------------------------------
__device__ __forceinline__ uint32_t smem_u32(const void* p) {
    uint32_t a;
    asm("{ .reg .u64 t; cvta.to.shared.u64 t, %1; cvt.u32.u64 %0, t; }" : "=r"(a) : "l"(p));
    return a;
}
__device__ __forceinline__ uint32_t f2tf32(float v) {
    uint32_t r;
    asm("cvt.rna.tf32.f32 %0, %1;" : "=r"(r) : "f"(v));
    return r;
}
__device__ __forceinline__ void tf32_split(uint32_t v, uint32_t& hi, uint32_t& lo) {
    float f = __uint_as_float(v);
    hi = f2tf32(f);
    lo = f2tf32(f - __uint_as_float(hi));
}
__device__ __forceinline__ void mma_tf32(float* c, const uint32_t* a, const uint32_t* b) {
    asm volatile("mma.sync.aligned.m16n8k8.row.col.f32.tf32.tf32.f32 "
        "{%0,%1,%2,%3},{%4,%5,%6,%7},{%8,%9},{%0,%1,%2,%3};"
        : "+f"(c[0]), "+f"(c[1]), "+f"(c[2]), "+f"(c[3])
        : "r"(a[0]), "r"(a[1]), "r"(a[2]), "r"(a[3]), "r"(b[0]), "r"(b[1]));
}
#define LDMATRIX_X4(r0, r1, r2, r3, addr) \
    asm volatile("ldmatrix.sync.aligned.m8n8.x4.shared.b16 {%0,%1,%2,%3}, [%4];" \
        : "=r"(r0), "=r"(r1), "=r"(r2), "=r"(r3) : "r"(addr))
#define CP_ASYNC16(dst, src) asm volatile("cp.async.cg.shared.global [%0], [%1], 16;" :: "r"(dst), "l"(src))
#define CP_COMMIT()          asm volatile("cp.async.commit_group;" ::: "memory")
#define CP_WAIT(n)           asm volatile("cp.async.wait_group %0;" :: "n"(n) : "memory")

__device__ __forceinline__ float sigf(float x) {
    return 1.f / (1.f + __expf(-x));
}

// ------------------- prep: weight transpose (fp32, no rounding) -------------
__global__ void __launch_bounds__(256)
transpose_kernel(const float* __restrict__ in, float* __restrict__ out, int K, int N)
{
    int idx = blockIdx.x * 256 + threadIdx.x;
    if (idx < K * N) {
        int n = idx / K, k = idx - n * K;
        out[idx] = in[k * N + n];
    }
}

// ---- near-fp32 GEMM + bias via 3-product split-tf32 mma -------------------
#define STAGE_BYTES 36864
__global__ void __launch_bounds__(256, 2)
gemm_mma_kernel(const float* __restrict__ A, const float* __restrict__ Wt,
                const float* __restrict__ bias, float* __restrict__ C,
                int M, int N, int K)
{
    extern __shared__ char smem[];
    const uint32_t smem_base = smem_u32(smem);
    const int tid = threadIdx.x;
    const int lane = tid & 31, wid = tid >> 5;
    const int m0 = blockIdx.x * 128, n0 = blockIdx.y * 128;
    const int wm = (wid >> 2) * 64, wn = (wid & 3) * 32;

    float acc[4][4][4];
    #pragma unroll
    for (int mt = 0; mt < 4; ++mt)
        #pragma unroll
        for (int nt = 0; nt < 4; ++nt)
            #pragma unroll
            for (int q = 0; q < 4; ++q) acc[mt][nt][q] = 0.f;

    const int rowsel = ((lane & 16) >> 1) + (lane & 7);
    const int colsel = ((lane >> 3) & 1) * 4;
    uint32_t offA[4], offB[2];
    #pragma unroll
    for (int mt = 0; mt < 4; ++mt)
        offA[mt] = (uint32_t)(((wm + mt * 16 + rowsel) * 36 + colsel) * 4);
    #pragma unroll
    for (int p = 0; p < 2; ++p)
        offB[p] = 18432u + (uint32_t)(((wn + p * 16 + rowsel) * 36 + colsel) * 4);

    const int nch = K >> 5;
    auto issue = [&](int ch, int stage) {
        const int kc = ch << 5;
        const uint32_t sA = smem_base + stage * STAGE_BYTES;
        const uint32_t sB = sA + 18432u;
        #pragma unroll
        for (int i = 0; i < 4; ++i) {
            int idx = tid + i * 256;
            int row = idx >> 3, c4 = idx & 7;
            CP_ASYNC16(sA + row * 144 + c4 * 16,
                       A + (size_t)(m0 + row) * K + kc + c4 * 4);
        }
        #pragma unroll
        for (int i = 0; i < 4; ++i) {
            int idx = tid + i * 256;
            int row = idx >> 3, c4 = idx & 7;
            CP_ASYNC16(sB + row * 144 + c4 * 16,
                       Wt + (size_t)(n0 + row) * K + kc + c4 * 4);
        }
        CP_COMMIT();
    };

    issue(0, 0);
    for (int ch = 0; ch < nch; ++ch) {
        if (ch + 1 < nch) { issue(ch + 1, (ch + 1) & 1); CP_WAIT(1); }
        else             { CP_WAIT(0); }
        __syncthreads();

        const uint32_t stg = smem_base + (ch & 1) * STAGE_BYTES;
        #pragma unroll
        for (int k8 = 0; k8 < 4; ++k8) {
            const uint32_t kb = (uint32_t)(k8 * 8 * 4);
            uint32_t braw[4][2], bhi[4][2], blo[4][2];
            #pragma unroll
            for (int p = 0; p < 2; ++p)
                LDMATRIX_X4(braw[2*p][0], braw[2*p][1], braw[2*p+1][0], braw[2*p+1][1],
                            stg + offB[p] + kb);
            #pragma unroll
            for (int nt = 0; nt < 4; ++nt)
                #pragma unroll
                for (int q = 0; q < 2; ++q)
                    tf32_split(braw[nt][q], bhi[nt][q], blo[nt][q]);

            #pragma unroll
            for (int mt = 0; mt < 4; ++mt) {
                uint32_t araw[4], ahi[4], alo[4];
                LDMATRIX_X4(araw[0], araw[2], araw[1], araw[3], stg + offA[mt] + kb);
                #pragma unroll
                for (int q = 0; q < 4; ++q) tf32_split(araw[q], ahi[q], alo[q]);
                #pragma unroll
                for (int nt = 0; nt < 4; ++nt) {
                    mma_tf32(acc[mt][nt], ahi, bhi[nt]);
                    mma_tf32(acc[mt][nt], ahi, blo[nt]);
                    mma_tf32(acc[mt][nt], alo, bhi[nt]);
                }
            }
        }
        __syncthreads();
    }

    #pragma unroll
    for (int mt = 0; mt < 4; ++mt) {
        int r = m0 + wm + mt * 16 + (lane >> 2);
        #pragma unroll
        for (int nt = 0; nt < 4; ++nt) {
            int col = n0 + wn + nt * 8 + (lane & 3) * 2;
            float b0 = __ldg(bias + col), b1 = __ldg(bias + col + 1);
            float2 v0 = make_float2(acc[mt][nt][0] + b0, acc[mt][nt][1] + b1);
            float2 v1 = make_float2(acc[mt][nt][2] + b0, acc[mt][nt][3] + b1);
            *(float2*)(C + (size_t)r * N + col)       = v0;
            *(float2*)(C + (size_t)(r + 8) * N + col) = v1;
        }
    }
}

// ------------------------- embedding MLP branch -----------------------------
__global__ void __launch_bounds__(256)
emb_mlp_kernel(const int* __restrict__ inputA, const float* __restrict__ emb,
               const float* __restrict__ w1, const float* __restrict__ b1,
               const float* __restrict__ w2, const float* __restrict__ b2,
               const float* __restrict__ w3, const float* __restrict__ b3,
               float* __restrict__ xout)
{
    __shared__ float x0[600], x1[256], x2[128];
    const int b = blockIdx.x, tid = threadIdx.x;
    for (int i = tid; i < 600; i += 256) {
        int la = i / 3, comp = i - la * 3;
        x0[i] = emb[inputA[b*200 + la]*3 + comp];
    }
    __syncthreads();
    {
        float acc = b1[tid];
        #pragma unroll 4
        for (int k = 0; k < 600; ++k) acc += x0[k] * w1[k*256 + tid];
        x1[tid] = fmaxf(acc, 0.f);
    }
    __syncthreads();
    if (tid < 128) {
        float acc = b2[tid];
        #pragma unroll 4
        for (int k = 0; k < 256; ++k) acc += x1[k] * w2[k*128 + tid];
        x2[tid] = fmaxf(acc, 0.f);
    }
    __syncthreads();
    if (tid < 64) {
        float acc = b3[tid];
        #pragma unroll 4
        for (int k = 0; k < 128; ++k) acc += x2[k] * w3[k*64 + tid];
        xout[b*64 + tid] = fmaxf(acc, 0.f);
    }
}

// ------------- LSTM layer 1 (H=128) — tensor-core recurrence v3 -------------
// v2 + FIX: ybuf is rank-local (64 cols); each CTA stores ONLY its own
// 64-column slice of Y. Arithmetic identical to R5 (rel_err 1.356e-4).
#define XS1 516                 // xg smem row stride (floats)
__global__ void __cluster_dims__(2,1,1) __launch_bounds__(256, 1)
lstm1_mma_kernel(const float* __restrict__ xg1f, const float* __restrict__ xg1b,
                 const float* __restrict__ r1f,  const float* __restrict__ r1b,
                 float* __restrict__ Y)
{
    extern __shared__ float sm[];
    float* sxg  = sm;                       // 2 * 16 * XS1
    float* hbuf = sm + 2 * 16 * XS1;        // 2 * 16 * 132
    float* ybuf = hbuf + 2 * 16 * 132;      // 16 * 68   (rank-local 64 cols)

    cg::cluster_group cl = cg::this_cluster();
    const int rank = cl.block_rank();
    const int dir  = blockIdx.y;
    const int b0   = (blockIdx.x >> 1) * 16;
    const int tid  = threadIdx.x;
    const int lane = tid & 31, w = tid >> 5;
    const int q    = lane & 3;
    const float* xg = dir ? xg1b : xg1f;
    const float* Wr = dir ? r1b : r1f;

    // register-resident weight fragments (verified mapping from R5)
    uint32_t bfr[4][16][2];
    #pragma unroll
    for (int nt = 0; nt < 4; ++nt) {
        int n_local = w * 32 + nt * 8 + (lane >> 2);
        int G = (n_local & 3) * 128 + rank * 64 + (n_local >> 2);
        #pragma unroll
        for (int kt = 0; kt < 16; ++kt)
            #pragma unroll
            for (int p = 0; p < 2; ++p)
                bfr[nt][kt][p] = f2tf32(Wr[(kt * 8 + q + p * 4) * 512 + G]);
    }

    for (int i = tid; i < 2 * 16 * 132; i += 256) hbuf[i] = 0.f;

    const int rowsel = ((lane & 16) >> 1) + (lane & 7);
    const int colsel = ((lane >> 3) & 1) * 4;
    const uint32_t hbase = smem_u32(hbuf);
    const uint32_t xbase = smem_u32(sxg);
    const bool isState = (lane & 1);
    const int g0 = (q & 1) * 2;
    int colA[4], hj[4], al[4];
    #pragma unroll
    for (int nt = 0; nt < 4; ++nt) {
        int a_local = w * 8 + nt * 2 + (q >> 1);
        colA[nt] = g0 * 128 + rank * 64 + a_local;
        hj[nt]   = rank * 64 + a_local;        // global h index (hbuf)
        al[nt]   = a_local;                    // local h index (ybuf)
    }
    const int r = lane >> 2;

    float cst[4][2];
    #pragma unroll
    for (int nt = 0; nt < 4; ++nt) { cst[nt][0] = 0.f; cst[nt][1] = 0.f; }

    // coalesced xg stage: 16 rows x 512 cols = 2048 float4, 8 per thread
    auto issue_xg = [&](int tt, int stage) {
        const uint32_t dst0 = xbase + (uint32_t)(stage * 16 * XS1 * 4);
        #pragma unroll
        for (int i = 0; i < 8; ++i) {
            int idx = tid + i * 256;
            int row = idx >> 7, c4 = idx & 127;
            CP_ASYNC16(dst0 + (uint32_t)((row * XS1 + c4 * 4) * 4),
                       xg + ((size_t)(b0 + row) * 512 + tt) * 512 + c4 * 4);
        }
        CP_COMMIT();
    };

    float* peer_h = cl.map_shared_rank(hbuf, rank ^ 1);
    __syncthreads();
    cl.sync();

    issue_xg(dir ? 511 : 0, 0);

    for (int t = 0; t < 512; ++t) {
        const int tt  = dir ? (511 - t) : t;
        const int cur = t & 1, nxt = cur ^ 1;

        if (t + 1 < 512) { issue_xg(dir ? (510 - t) : (t + 1), nxt); CP_WAIT(1); }
        else             { CP_WAIT(0); }
        __syncthreads();   // xg[cur] visible; also fences ybuf reuse

        // acc init = xg
        const float* xs = sxg + cur * 16 * XS1;
        float acc[4][4];
        #pragma unroll
        for (int nt = 0; nt < 4; ++nt) {
            acc[nt][0] = xs[r * XS1 + colA[nt]];
            acc[nt][1] = xs[r * XS1 + colA[nt] + 128];
            acc[nt][2] = xs[(r + 8) * XS1 + colA[nt]];
            acc[nt][3] = xs[(r + 8) * XS1 + colA[nt] + 128];
        }

        // h @ Wr via mma
        const uint32_t abase = hbase + (uint32_t)(cur * 16 * 132 * 4);
        #pragma unroll
        for (int kt = 0; kt < 16; ++kt) {
            uint32_t a0, a1, a2, a3;
            LDMATRIX_X4(a0, a2, a1, a3,
                        abase + (uint32_t)((rowsel * 132 + kt * 8 + colsel) * 4));
            uint32_t afr[4] = {a0, a1, a2, a3};
            #pragma unroll
            for (int nt = 0; nt < 4; ++nt)
                mma_tf32(acc[nt], afr, bfr[nt][kt]);
        }

        // activations + state update
        #pragma unroll
        for (int nt = 0; nt < 4; ++nt) {
            float v0 = isState ? fmaxf(acc[nt][0], 0.f) : sigf(acc[nt][0]);
            float v1 = sigf(acc[nt][1]);
            float v2 = isState ? fmaxf(acc[nt][2], 0.f) : sigf(acc[nt][2]);
            float v3 = sigf(acc[nt][3]);
            float s0 = __shfl_xor_sync(0xffffffffu, v0, 1);
            float s1 = __shfl_xor_sync(0xffffffffu, v1, 1);
            float s2 = __shfl_xor_sync(0xffffffffu, v2, 1);
            float s3 = __shfl_xor_sync(0xffffffffu, v3, 1);
            if (isState) {
                float c0 = s1 * cst[nt][0] + s0 * v0;
                float c1 = s3 * cst[nt][1] + s2 * v2;
                cst[nt][0] = c0; cst[nt][1] = c1;
                float h0 = v1 * fmaxf(c0, 0.f);
                float h1 = v3 * fmaxf(c1, 0.f);
                float h0r = __uint_as_float(f2tf32(h0));
                float h1r = __uint_as_float(f2tf32(h1));
                int o0 = nxt * 16 * 132 + r * 132 + hj[nt];
                int o1 = nxt * 16 * 132 + (r + 8) * 132 + hj[nt];
                hbuf[o0] = h0r;  hbuf[o1] = h1r;
                peer_h[o0] = h0r; peer_h[o1] = h1r;
                ybuf[r * 68 + al[nt]]       = h0;     // rank-local columns only
                ybuf[(r + 8) * 68 + al[nt]] = h1;
            }
        }
        cl.sync();

        // coalesced Y store: this CTA's own 64-column slice only.
        // 256 threads = 256 float4 = 16 rows x 16 float4 (64 floats).
        {
            int row = tid >> 4, c4 = tid & 15;
            float4 v = *(const float4*)&ybuf[row * 68 + c4 * 4];
            *(float4*)&Y[((size_t)(b0 + row) * 512 + tt) * 256
                         + dir * 128 + rank * 64 + c4 * 4] = v;
        }
    }
}

// ------------- LSTM layer 2 (H=64) — tensor-core recurrence v2 --------------
#define XS2 260
__global__ void __launch_bounds__(256, 1)
lstm2_mma_kernel(const float* __restrict__ xg2f, const float* __restrict__ xg2b,
                 const float* __restrict__ r2f,  const float* __restrict__ r2b,
                 float* __restrict__ hout)
{
    extern __shared__ float sm[];
    float* sxg  = sm;                       // 2 * 16 * XS2
    float* hbuf = sm + 2 * 16 * XS2;        // 2 * 16 * 68

    const int dir = blockIdx.y;
    const int b0  = blockIdx.x * 16;
    const int tid = threadIdx.x;
    const int lane = tid & 31, w = tid >> 5;
    const int q = lane & 3;
    const float* xg = dir ? xg2b : xg2f;
    const float* Wr = dir ? r2b : r2f;

    uint32_t bfr[4][8][2];
    #pragma unroll
    for (int nt = 0; nt < 4; ++nt) {
        int n_local = w * 32 + nt * 8 + (lane >> 2);
        int G = (n_local & 3) * 64 + (n_local >> 2);
        #pragma unroll
        for (int kt = 0; kt < 8; ++kt)
            #pragma unroll
            for (int p = 0; p < 2; ++p)
                bfr[nt][kt][p] = f2tf32(Wr[(kt * 8 + q + p * 4) * 256 + G]);
    }

    for (int i = tid; i < 2 * 16 * 68; i += 256) hbuf[i] = 0.f;

    const int rowsel = ((lane & 16) >> 1) + (lane & 7);
    const int colsel = ((lane >> 3) & 1) * 4;
    const uint32_t hbase = smem_u32(hbuf);
    const uint32_t xbase = smem_u32(sxg);
    const bool isState = (lane & 1);
    const int g0 = (q & 1) * 2;
    int colA[4], hj[4];
    #pragma unroll
    for (int nt = 0; nt < 4; ++nt) {
        int a_local = w * 8 + nt * 2 + (q >> 1);
        colA[nt] = g0 * 64 + a_local;
        hj[nt]   = a_local;
    }
    const int r = lane >> 2;

    float cst[4][2];
    #pragma unroll
    for (int nt = 0; nt < 4; ++nt) { cst[nt][0] = 0.f; cst[nt][1] = 0.f; }

    auto issue_xg = [&](int tt, int stage) {
        const uint32_t dst0 = xbase + (uint32_t)(stage * 16 * XS2 * 4);
        #pragma unroll
        for (int i = 0; i < 4; ++i) {
            int idx = tid + i * 256;
            int row = idx >> 6, c4 = idx & 63;
            CP_ASYNC16(dst0 + (uint32_t)((row * XS2 + c4 * 4) * 4),
                       xg + ((size_t)(b0 + row) * 512 + tt) * 256 + c4 * 4);
        }
        CP_COMMIT();
    };

    __syncthreads();
    issue_xg(dir ? 511 : 0, 0);

    for (int t = 0; t < 512; ++t) {
        const int tt  = dir ? (511 - t) : t;
        const int cur = t & 1, nxt = cur ^ 1;

        if (t + 1 < 512) { issue_xg(dir ? (510 - t) : (t + 1), nxt); CP_WAIT(1); }
        else             { CP_WAIT(0); }
        __syncthreads();

        const float* xs = sxg + cur * 16 * XS2;
        float acc[4][4];
        #pragma unroll
        for (int nt = 0; nt < 4; ++nt) {
            acc[nt][0] = xs[r * XS2 + colA[nt]];
            acc[nt][1] = xs[r * XS2 + colA[nt] + 64];
            acc[nt][2] = xs[(r + 8) * XS2 + colA[nt]];
            acc[nt][3] = xs[(r + 8) * XS2 + colA[nt] + 64];
        }

        const uint32_t abase = hbase + (uint32_t)(cur * 16 * 68 * 4);
        #pragma unroll
        for (int kt = 0; kt < 8; ++kt) {
            uint32_t a0, a1, a2, a3;
            LDMATRIX_X4(a0, a2, a1, a3,
                        abase + (uint32_t)((rowsel * 68 + kt * 8 + colsel) * 4));
            uint32_t afr[4] = {a0, a1, a2, a3};
            #pragma unroll
            for (int nt = 0; nt < 4; ++nt)
                mma_tf32(acc[nt], afr, bfr[nt][kt]);
        }

        #pragma unroll
        for (int nt = 0; nt < 4; ++nt) {
            float v0 = isState ? fmaxf(acc[nt][0], 0.f) : sigf(acc[nt][0]);
            float v1 = sigf(acc[nt][1]);
            float v2 = isState ? fmaxf(acc[nt][2], 0.f) : sigf(acc[nt][2]);
            float v3 = sigf(acc[nt][3]);
            float s0 = __shfl_xor_sync(0xffffffffu, v0, 1);
            float s1 = __shfl_xor_sync(0xffffffffu, v1, 1);
            float s2 = __shfl_xor_sync(0xffffffffu, v2, 1);
            float s3 = __shfl_xor_sync(0xffffffffu, v3, 1);
            if (isState) {
                float c0 = s1 * cst[nt][0] + s0 * v0;
                float c1 = s3 * cst[nt][1] + s2 * v2;
                cst[nt][0] = c0; cst[nt][1] = c1;
                float h0 = v1 * fmaxf(c0, 0.f);
                float h1 = v3 * fmaxf(c1, 0.f);
                hbuf[nxt * 16 * 68 + r * 68 + hj[nt]]       = __uint_as_float(f2tf32(h0));
                hbuf[nxt * 16 * 68 + (r + 8) * 68 + hj[nt]] = __uint_as_float(f2tf32(h1));
                if (t == 511) {
                    hout[(size_t)(b0 + r) * 128 + dir * 64 + hj[nt]]     = h0;
                    hout[(size_t)(b0 + r + 8) * 128 + dir * 64 + hj[nt]] = h1;
                }
            }
        }
        __syncthreads();
    }
}

// ------------------------------ heads ---------------------------------------
__global__ void __launch_bounds__(256)
head_kernel(const float* __restrict__ x64, const float* __restrict__ h2,
            const float* __restrict__ wz1, const float* __restrict__ bz1,
            const float* __restrict__ wz2, const float* __restrict__ bz2,
            const float* __restrict__ wt1, const float* __restrict__ bt1,
            const float* __restrict__ wt2, const float* __restrict__ bt2,
            float* __restrict__ out)
{
    const int b = threadIdx.x;
    float comb[192];
    #pragma unroll 4
    for (int k = 0; k < 64; ++k)  comb[k]      = x64[b*64 + k];
    #pragma unroll 4
    for (int k = 0; k < 128; ++k) comb[64 + k] = h2[b*128 + k];

    float z0 = bz1[0], z1 = bz1[1], t0 = bt1[0], t1 = bt1[1];
    #pragma unroll 4
    for (int k = 0; k < 192; ++k) {
        float v = comb[k];
        z0 += v * wz1[k*2 + 0]; z1 += v * wz1[k*2 + 1];
        t0 += v * wt1[k*2 + 0]; t1 += v * wt1[k*2 + 1];
    }
    out[b]       = fmaxf(z0,0.f)*wz2[0] + fmaxf(z1,0.f)*wz2[1] + bz2[0];
    out[256 + b] = fmaxf(t0,0.f)*wt2[0] + fmaxf(t1,0.f)*wt2[1] + bt2[0];
}

// ------------------------------ launcher ------------------------------------
extern "C" void kernel_launch(void* const* d_in, const int* in_sizes, int n_in,
                              void* d_out, int out_size)
{
    const int*   inputA = (const int*)  d_in[0];
    const float* inputB = (const float*)d_in[1];
    const float* emb = (const float*)d_in[2];
    const float *w1=(const float*)d_in[3],  *b1=(const float*)d_in[4];
    const float *w2=(const float*)d_in[5],  *b2=(const float*)d_in[6];
    const float *w3=(const float*)d_in[7],  *b3=(const float*)d_in[8];
    const float *k1f=(const float*)d_in[9],  *r1f=(const float*)d_in[10], *bb1f=(const float*)d_in[11];
    const float *k1b=(const float*)d_in[12], *r1b=(const float*)d_in[13], *bb1b=(const float*)d_in[14];
    const float *k2f=(const float*)d_in[15], *r2f=(const float*)d_in[16], *bb2f=(const float*)d_in[17];
    const float *k2b=(const float*)d_in[18], *r2b=(const float*)d_in[19], *bb2b=(const float*)d_in[20];
    const float *wz1=(const float*)d_in[21], *bz1=(const float*)d_in[22];
    const float *wz2=(const float*)d_in[23], *bz2=(const float*)d_in[24];
    const float *wt1=(const float*)d_in[25], *bt1=(const float*)d_in[26];
    const float *wt2=(const float*)d_in[27], *bt2=(const float*)d_in[28];
    float* out = (float*)d_out;

    float *xg1f, *xg1b, *Y, *xg2f, *xg2b, *x64, *h2, *wT;
    cudaGetSymbolAddress((void**)&xg1f, g_xg1f);
    cudaGetSymbolAddress((void**)&xg1b, g_xg1b);
    cudaGetSymbolAddress((void**)&Y,    g_Y);
    cudaGetSymbolAddress((void**)&xg2f, g_xg2f);
    cudaGetSymbolAddress((void**)&xg2b, g_xg2b);
    cudaGetSymbolAddress((void**)&x64,  g_x64);
    cudaGetSymbolAddress((void**)&h2,   g_h2);
    cudaGetSymbolAddress((void**)&wT,   g_wT);
    float* wt1f = wT;
    float* wt1b = wT + 65536;
    float* wt2f = wT + 2*65536;
    float* wt2b = wT + 3*65536;

    const size_t sm1 = (size_t)(2*16*XS1 + 2*16*132 + 16*68) * sizeof(float);
    const size_t sm2 = (size_t)(2*16*XS2 + 2*16*68) * sizeof(float);

    static bool attr_done = false;
    if (!attr_done) {
        cudaFuncSetAttribute(gemm_mma_kernel, cudaFuncAttributeMaxDynamicSharedMemorySize, 2*STAGE_BYTES);
        cudaFuncSetAttribute(lstm1_mma_kernel, cudaFuncAttributeMaxDynamicSharedMemorySize, (int)sm1);
        cudaFuncSetAttribute(lstm2_mma_kernel, cudaFuncAttributeMaxDynamicSharedMemorySize, (int)sm2);
        attr_done = true;
    }

    transpose_kernel<<<(65536+255)/256, 256>>>(k1f, wt1f, 128, 512);
    transpose_kernel<<<(65536+255)/256, 256>>>(k1b, wt1b, 128, 512);
    transpose_kernel<<<(65536+255)/256, 256>>>(k2f, wt2f, 256, 256);
    transpose_kernel<<<(65536+255)/256, 256>>>(k2b, wt2b, 256, 256);

    emb_mlp_kernel<<<256, 256>>>(inputA, emb, w1,b1, w2,b2, w3,b3, x64);

    const size_t gsm = 2*STAGE_BYTES;
    gemm_mma_kernel<<<dim3(1024,4), 256, gsm>>>(inputB, wt1f, bb1f, xg1f, BT, 512, 128);
    gemm_mma_kernel<<<dim3(1024,4), 256, gsm>>>(inputB, wt1b, bb1b, xg1b, BT, 512, 128);

    lstm1_mma_kernel<<<dim3(32,2), 256, sm1>>>(xg1f, xg1b, r1f, r1b, Y);

    gemm_mma_kernel<<<dim3(1024,2), 256, gsm>>>(Y, wt2f, bb2f, xg2f, BT, 256, 256);
    gemm_mma_kernel<<<dim3(1024,2), 256, gsm>>>(Y, wt2b, bb2b, xg2b, BT, 256, 256);

    lstm2_mma_kernel<<<dim3(16,2), 256, sm2>>>(xg2f, xg2b, r2f, r2b, h2);

    head_kernel<<<1, 256>>>(x64, h2, wz1,bz1, wz2,bz2, wt1,bt1, wt2,bt2, out);
}

// round 9
// speedup vs baseline: 1.4000x; 1.1024x over previous
#include <cuda_runtime.h>
#include <cuda_bf16.h>
#include <cooperative_groups.h>
#include <cstdint>
namespace cg = cooperative_groups;

// ------------------------- scratch (device globals) -------------------------
#define BT (256*512)
__device__ float g_x64 [256*64];
__device__ float g_xg1f[(size_t)BT*512];
__device__ float g_xg1b[(size_t)BT*512];
__device__ float g_xg2f[(size_t)BT*256];
__device__ float g_xg2b[(size_t)BT*256];
__device__ float g_h2  [256*128];
__device__ __nv_bfloat16 g_xBhi[(size_t)BT*128];
__device__ __nv_bfloat16 g_xBlo[(size_t)BT*128];
__device__ __nv_bfloat16 g_Yhi [(size_t)BT*256];
__device__ __nv_bfloat16 g_Ylo [(size_t)BT*256];
__device__ __nv_bfloat16 g_wThi[4*65536];
__device__ __nv_bfloat16 g_wTlo[4*65536];

// ------------------------- small PTX helpers --------------------------------
__device__ __forceinline__ uint32_t smem_u32(const void* p) {
    uint32_t a;
    asm("{ .reg .u64 t; cvta.to.shared.u64 t, %1; cvt.u32.u64 %0, t; }" : "=r"(a) : "l"(p));
    return a;
}
__device__ __forceinline__ uint32_t f2tf32(float v) {
    uint32_t r;
    asm("cvt.rna.tf32.f32 %0, %1;" : "=r"(r) : "f"(v));
    return r;
}
__device__ __forceinline__ void mma_tf32(float* c, const uint32_t* a, const uint32_t* b) {
    asm volatile("mma.sync.aligned.m16n8k8.row.col.f32.tf32.tf32.f32 "
        "{%0,%1,%2,%3},{%4,%5,%6,%7},{%8,%9},{%0,%1,%2,%3};"
        : "+f"(c[0]), "+f"(c[1]), "+f"(c[2]), "+f"(c[3])
        : "r"(a[0]), "r"(a[1]), "r"(a[2]), "r"(a[3]), "r"(b[0]), "r"(b[1]));
}
__device__ __forceinline__ void mma_bf16(float* c, const uint32_t* a, const uint32_t* b) {
    asm volatile("mma.sync.aligned.m16n8k16.row.col.f32.bf16.bf16.f32 "
        "{%0,%1,%2,%3},{%4,%5,%6,%7},{%8,%9},{%0,%1,%2,%3};"
        : "+f"(c[0]), "+f"(c[1]), "+f"(c[2]), "+f"(c[3])
        : "r"(a[0]), "r"(a[1]), "r"(a[2]), "r"(a[3]), "r"(b[0]), "r"(b[1]));
}
#define LDMATRIX_X4(r0, r1, r2, r3, addr) \
    asm volatile("ldmatrix.sync.aligned.m8n8.x4.shared.b16 {%0,%1,%2,%3}, [%4];" \
        : "=r"(r0), "=r"(r1), "=r"(r2), "=r"(r3) : "r"(addr))
#define CP_ASYNC16(dst, src) asm volatile("cp.async.cg.shared.global [%0], [%1], 16;" :: "r"(dst), "l"(src))
#define CP_COMMIT()          asm volatile("cp.async.commit_group;" ::: "memory")
#define CP_WAIT(n)           asm volatile("cp.async.wait_group %0;" :: "n"(n) : "memory")

__device__ __forceinline__ float sigf(float x) {
    return 1.f / (1.f + __expf(-x));
}
__device__ __forceinline__ uint32_t pack_bf2(__nv_bfloat16 a, __nv_bfloat16 b) {
    __nv_bfloat162 t = __halves2bfloat162(a, b);
    return *(uint32_t*)&t;
}
__device__ __forceinline__ void split_bf(float f, __nv_bfloat16& hi, __nv_bfloat16& lo) {
    hi = __float2bfloat16(f);
    lo = __float2bfloat16(f - __bfloat162float(hi));
}

// ------------------- prep: bf16 split / transpose+split ---------------------
__global__ void __launch_bounds__(256)
split_kernel(const float* __restrict__ in, __nv_bfloat16* __restrict__ hi,
             __nv_bfloat16* __restrict__ lo, int n4)
{
    int i = blockIdx.x * 256 + threadIdx.x;
    if (i < n4) {
        float4 v = ((const float4*)in)[i];
        __nv_bfloat16 h0,h1,h2,h3,l0,l1,l2,l3;
        split_bf(v.x,h0,l0); split_bf(v.y,h1,l1);
        split_bf(v.z,h2,l2); split_bf(v.w,h3,l3);
        ((uint2*)hi)[i] = make_uint2(pack_bf2(h0,h1), pack_bf2(h2,h3));
        ((uint2*)lo)[i] = make_uint2(pack_bf2(l0,l1), pack_bf2(l2,l3));
    }
}
__global__ void __launch_bounds__(256)
transpose_split_kernel(const float* __restrict__ in, __nv_bfloat16* __restrict__ hi,
                       __nv_bfloat16* __restrict__ lo, int K, int N)
{
    int idx = blockIdx.x * 256 + threadIdx.x;
    if (idx < K * N) {
        int n = idx / K, k = idx - n * K;
        __nv_bfloat16 h, l;
        split_bf(in[k * N + n], h, l);
        hi[idx] = h; lo[idx] = l;
    }
}

// ---- bf16x3 GEMM + bias: C[M,N] = A[M,K] @ Wt[N,K]^T + b -------------------
// A/Wt pre-split into bf16 hi/lo. Block 128x128, BK=32, 2-stage cp.async,
// 8 warps (2m x 4n), warp tile 64x32, m16n8k16 fragments, 3 products.
// SMEM stage: Ahi/Alo/Bhi/Blo each 128 rows x 40 bf16 (80B stride) = 10240B.
#define GSTAGE 40960
__global__ void __launch_bounds__(256, 2)
gemm_bf16_kernel(const __nv_bfloat16* __restrict__ Ahi, const __nv_bfloat16* __restrict__ Alo,
                 const __nv_bfloat16* __restrict__ Whi, const __nv_bfloat16* __restrict__ Wlo,
                 const float* __restrict__ bias, float* __restrict__ C,
                 int M, int N, int K)
{
    extern __shared__ char smem[];
    const uint32_t smem_base = smem_u32(smem);
    const int tid = threadIdx.x;
    const int lane = tid & 31, wid = tid >> 5;
    const int m0 = blockIdx.x * 128, n0 = blockIdx.y * 128;
    const int wm = (wid >> 2) * 64, wn = (wid & 3) * 32;

    float acc[4][4][4];
    #pragma unroll
    for (int mt = 0; mt < 4; ++mt)
        #pragma unroll
        for (int nt = 0; nt < 4; ++nt)
            #pragma unroll
            for (int q = 0; q < 4; ++q) acc[mt][nt][q] = 0.f;

    // ldmatrix b16 x4 addressing on 16x16 tiles: row = lane&15, +16B for lane>=16
    const uint32_t lrow = (uint32_t)(lane & 15);
    const uint32_t lcol = (uint32_t)((lane >> 4) * 16);
    uint32_t offA[4], offB[2];
    #pragma unroll
    for (int mt = 0; mt < 4; ++mt)
        offA[mt] = (uint32_t)(wm + mt * 16 + lrow) * 80u + lcol;
    #pragma unroll
    for (int p = 0; p < 2; ++p)
        offB[p] = (uint32_t)(wn + p * 16 + lrow) * 80u + lcol;

    const int nch = K >> 5;
    auto issue = [&](int ch, int stage) {
        const int kc = ch << 5;
        const uint32_t st = smem_base + (uint32_t)stage * GSTAGE;
        #pragma unroll
        for (int i = 0; i < 2; ++i) {
            int idx = tid + i * 256;                 // 0..511
            int row = idx >> 2, c = idx & 3;         // 128 rows x 4 x 16B
            uint32_t soff = (uint32_t)(row * 80 + c * 16);
            size_t ga = (size_t)(m0 + row) * K + kc + c * 8;
            size_t gb = (size_t)(n0 + row) * K + kc + c * 8;
            CP_ASYNC16(st + soff,           Ahi + ga);
            CP_ASYNC16(st + 10240u + soff,  Alo + ga);
            CP_ASYNC16(st + 20480u + soff,  Whi + gb);
            CP_ASYNC16(st + 30720u + soff,  Wlo + gb);
        }
        CP_COMMIT();
    };

    issue(0, 0);
    for (int ch = 0; ch < nch; ++ch) {
        if (ch + 1 < nch) { issue(ch + 1, (ch + 1) & 1); CP_WAIT(1); }
        else             { CP_WAIT(0); }
        __syncthreads();

        const uint32_t stg = smem_base + (uint32_t)(ch & 1) * GSTAGE;
        #pragma unroll
        for (int kk = 0; kk < 2; ++kk) {             // two k16 steps per chunk
            const uint32_t kb = (uint32_t)(kk * 32); // 16 bf16 = 32B

            uint32_t bhi[4][2], blo[4][2];
            #pragma unroll
            for (int p = 0; p < 2; ++p) {
                uint32_t r0, r1, r2, r3;
                LDMATRIX_X4(r0, r1, r2, r3, stg + 20480u + offB[p] + kb);
                bhi[2*p][0] = r0; bhi[2*p+1][0] = r1;
                bhi[2*p][1] = r2; bhi[2*p+1][1] = r3;
                LDMATRIX_X4(r0, r1, r2, r3, stg + 30720u + offB[p] + kb);
                blo[2*p][0] = r0; blo[2*p+1][0] = r1;
                blo[2*p][1] = r2; blo[2*p+1][1] = r3;
            }

            #pragma unroll
            for (int mt = 0; mt < 4; ++mt) {
                uint32_t ahi[4], alo[4];
                LDMATRIX_X4(ahi[0], ahi[1], ahi[2], ahi[3], stg + offA[mt] + kb);
                LDMATRIX_X4(alo[0], alo[1], alo[2], alo[3], stg + 10240u + offA[mt] + kb);
                #pragma unroll
                for (int nt = 0; nt < 4; ++nt) {
                    mma_bf16(acc[mt][nt], ahi, bhi[nt]);
                    mma_bf16(acc[mt][nt], ahi, blo[nt]);
                    mma_bf16(acc[mt][nt], alo, bhi[nt]);
                }
            }
        }
        __syncthreads();
    }

    #pragma unroll
    for (int mt = 0; mt < 4; ++mt) {
        int r = m0 + wm + mt * 16 + (lane >> 2);
        #pragma unroll
        for (int nt = 0; nt < 4; ++nt) {
            int col = n0 + wn + nt * 8 + (lane & 3) * 2;
            float b0 = __ldg(bias + col), b1 = __ldg(bias + col + 1);
            float2 v0 = make_float2(acc[mt][nt][0] + b0, acc[mt][nt][1] + b1);
            float2 v1 = make_float2(acc[mt][nt][2] + b0, acc[mt][nt][3] + b1);
            *(float2*)(C + (size_t)r * N + col)       = v0;
            *(float2*)(C + (size_t)(r + 8) * N + col) = v1;
        }
    }
}

// ------------------------- embedding MLP branch -----------------------------
__global__ void __launch_bounds__(256)
emb_mlp_kernel(const int* __restrict__ inputA, const float* __restrict__ emb,
               const float* __restrict__ w1, const float* __restrict__ b1,
               const float* __restrict__ w2, const float* __restrict__ b2,
               const float* __restrict__ w3, const float* __restrict__ b3,
               float* __restrict__ xout)
{
    __shared__ float x0[600], x1[256], x2[128];
    const int b = blockIdx.x, tid = threadIdx.x;
    for (int i = tid; i < 600; i += 256) {
        int la = i / 3, comp = i - la * 3;
        x0[i] = emb[inputA[b*200 + la]*3 + comp];
    }
    __syncthreads();
    {
        float acc = b1[tid];
        #pragma unroll 4
        for (int k = 0; k < 600; ++k) acc += x0[k] * w1[k*256 + tid];
        x1[tid] = fmaxf(acc, 0.f);
    }
    __syncthreads();
    if (tid < 128) {
        float acc = b2[tid];
        #pragma unroll 4
        for (int k = 0; k < 256; ++k) acc += x1[k] * w2[k*128 + tid];
        x2[tid] = fmaxf(acc, 0.f);
    }
    __syncthreads();
    if (tid < 64) {
        float acc = b3[tid];
        #pragma unroll 4
        for (int k = 0; k < 128; ++k) acc += x2[k] * w3[k*64 + tid];
        xout[b*64 + tid] = fmaxf(acc, 0.f);
    }
}

// ------------- LSTM layer 1 (H=128) — tensor-core recurrence v4 -------------
// R7 (verified) + Y stored directly as bf16 hi/lo pair for the bf16x3 GEMM2.
#define XS1 516
__global__ void __cluster_dims__(2,1,1) __launch_bounds__(256, 1)
lstm1_mma_kernel(const float* __restrict__ xg1f, const float* __restrict__ xg1b,
                 const float* __restrict__ r1f,  const float* __restrict__ r1b,
                 __nv_bfloat16* __restrict__ Yhi, __nv_bfloat16* __restrict__ Ylo)
{
    extern __shared__ float sm[];
    float* sxg  = sm;                       // 2 * 16 * XS1
    float* hbuf = sm + 2 * 16 * XS1;        // 2 * 16 * 132
    float* ybuf = hbuf + 2 * 16 * 132;      // 16 * 68 (rank-local)

    cg::cluster_group cl = cg::this_cluster();
    const int rank = cl.block_rank();
    const int dir  = blockIdx.y;
    const int b0   = (blockIdx.x >> 1) * 16;
    const int tid  = threadIdx.x;
    const int lane = tid & 31, w = tid >> 5;
    const int q    = lane & 3;
    const float* xg = dir ? xg1b : xg1f;
    const float* Wr = dir ? r1b : r1f;

    uint32_t bfr[4][16][2];
    #pragma unroll
    for (int nt = 0; nt < 4; ++nt) {
        int n_local = w * 32 + nt * 8 + (lane >> 2);
        int G = (n_local & 3) * 128 + rank * 64 + (n_local >> 2);
        #pragma unroll
        for (int kt = 0; kt < 16; ++kt)
            #pragma unroll
            for (int p = 0; p < 2; ++p)
                bfr[nt][kt][p] = f2tf32(Wr[(kt * 8 + q + p * 4) * 512 + G]);
    }

    for (int i = tid; i < 2 * 16 * 132; i += 256) hbuf[i] = 0.f;

    const int rowsel = ((lane & 16) >> 1) + (lane & 7);
    const int colsel = ((lane >> 3) & 1) * 4;
    const uint32_t hbase = smem_u32(hbuf);
    const uint32_t xbase = smem_u32(sxg);
    const bool isState = (lane & 1);
    const int g0 = (q & 1) * 2;
    int colA[4], hj[4], al[4];
    #pragma unroll
    for (int nt = 0; nt < 4; ++nt) {
        int a_local = w * 8 + nt * 2 + (q >> 1);
        colA[nt] = g0 * 128 + rank * 64 + a_local;
        hj[nt]   = rank * 64 + a_local;
        al[nt]   = a_local;
    }
    const int r = lane >> 2;

    float cst[4][2];
    #pragma unroll
    for (int nt = 0; nt < 4; ++nt) { cst[nt][0] = 0.f; cst[nt][1] = 0.f; }

    auto issue_xg = [&](int tt, int stage) {
        const uint32_t dst0 = xbase + (uint32_t)(stage * 16 * XS1 * 4);
        #pragma unroll
        for (int i = 0; i < 8; ++i) {
            int idx = tid + i * 256;
            int row = idx >> 7, c4 = idx & 127;
            CP_ASYNC16(dst0 + (uint32_t)((row * XS1 + c4 * 4) * 4),
                       xg + ((size_t)(b0 + row) * 512 + tt) * 512 + c4 * 4);
        }
        CP_COMMIT();
    };

    float* peer_h = cl.map_shared_rank(hbuf, rank ^ 1);
    __syncthreads();
    cl.sync();

    issue_xg(dir ? 511 : 0, 0);

    for (int t = 0; t < 512; ++t) {
        const int tt  = dir ? (511 - t) : t;
        const int cur = t & 1, nxt = cur ^ 1;

        if (t + 1 < 512) { issue_xg(dir ? (510 - t) : (t + 1), nxt); CP_WAIT(1); }
        else             { CP_WAIT(0); }
        __syncthreads();

        const float* xs = sxg + cur * 16 * XS1;
        float acc[4][4];
        #pragma unroll
        for (int nt = 0; nt < 4; ++nt) {
            acc[nt][0] = xs[r * XS1 + colA[nt]];
            acc[nt][1] = xs[r * XS1 + colA[nt] + 128];
            acc[nt][2] = xs[(r + 8) * XS1 + colA[nt]];
            acc[nt][3] = xs[(r + 8) * XS1 + colA[nt] + 128];
        }

        const uint32_t abase = hbase + (uint32_t)(cur * 16 * 132 * 4);
        #pragma unroll
        for (int kt = 0; kt < 16; ++kt) {
            uint32_t a0, a1, a2, a3;
            LDMATRIX_X4(a0, a2, a1, a3,
                        abase + (uint32_t)((rowsel * 132 + kt * 8 + colsel) * 4));
            uint32_t afr[4] = {a0, a1, a2, a3};
            #pragma unroll
            for (int nt = 0; nt < 4; ++nt)
                mma_tf32(acc[nt], afr, bfr[nt][kt]);
        }

        #pragma unroll
        for (int nt = 0; nt < 4; ++nt) {
            float v0 = isState ? fmaxf(acc[nt][0], 0.f) : sigf(acc[nt][0]);
            float v1 = sigf(acc[nt][1]);
            float v2 = isState ? fmaxf(acc[nt][2], 0.f) : sigf(acc[nt][2]);
            float v3 = sigf(acc[nt][3]);
            float s0 = __shfl_xor_sync(0xffffffffu, v0, 1);
            float s1 = __shfl_xor_sync(0xffffffffu, v1, 1);
            float s2 = __shfl_xor_sync(0xffffffffu, v2, 1);
            float s3 = __shfl_xor_sync(0xffffffffu, v3, 1);
            if (isState) {
                float c0 = s1 * cst[nt][0] + s0 * v0;
                float c1 = s3 * cst[nt][1] + s2 * v2;
                cst[nt][0] = c0; cst[nt][1] = c1;
                float h0 = v1 * fmaxf(c0, 0.f);
                float h1 = v3 * fmaxf(c1, 0.f);
                float h0r = __uint_as_float(f2tf32(h0));
                float h1r = __uint_as_float(f2tf32(h1));
                int o0 = nxt * 16 * 132 + r * 132 + hj[nt];
                int o1 = nxt * 16 * 132 + (r + 8) * 132 + hj[nt];
                hbuf[o0] = h0r;  hbuf[o1] = h1r;
                peer_h[o0] = h0r; peer_h[o1] = h1r;
                ybuf[r * 68 + al[nt]]       = h0;
                ybuf[(r + 8) * 68 + al[nt]] = h1;
            }
        }
        cl.sync();

        // coalesced Y store: own 64-col slice, split into bf16 hi/lo
        {
            int row = tid >> 4, c4 = tid & 15;
            float4 v = *(const float4*)&ybuf[row * 68 + c4 * 4];
            size_t idx = ((size_t)(b0 + row) * 512 + tt) * 256
                         + dir * 128 + rank * 64 + c4 * 4;
            __nv_bfloat16 h0,h1,h2,h3,l0,l1,l2,l3;
            split_bf(v.x,h0,l0); split_bf(v.y,h1,l1);
            split_bf(v.z,h2,l2); split_bf(v.w,h3,l3);
            *(uint2*)&Yhi[idx] = make_uint2(pack_bf2(h0,h1), pack_bf2(h2,h3));
            *(uint2*)&Ylo[idx] = make_uint2(pack_bf2(l0,l1), pack_bf2(l2,l3));
        }
    }
}

// ------------- LSTM layer 2 (H=64) — tensor-core recurrence (R7) ------------
#define XS2 260
__global__ void __launch_bounds__(256, 1)
lstm2_mma_kernel(const float* __restrict__ xg2f, const float* __restrict__ xg2b,
                 const float* __restrict__ r2f,  const float* __restrict__ r2b,
                 float* __restrict__ hout)
{
    extern __shared__ float sm[];
    float* sxg  = sm;
    float* hbuf = sm + 2 * 16 * XS2;

    const int dir = blockIdx.y;
    const int b0  = blockIdx.x * 16;
    const int tid = threadIdx.x;
    const int lane = tid & 31, w = tid >> 5;
    const int q = lane & 3;
    const float* xg = dir ? xg2b : xg2f;
    const float* Wr = dir ? r2b : r2f;

    uint32_t bfr[4][8][2];
    #pragma unroll
    for (int nt = 0; nt < 4; ++nt) {
        int n_local = w * 32 + nt * 8 + (lane >> 2);
        int G = (n_local & 3) * 64 + (n_local >> 2);
        #pragma unroll
        for (int kt = 0; kt < 8; ++kt)
            #pragma unroll
            for (int p = 0; p < 2; ++p)
                bfr[nt][kt][p] = f2tf32(Wr[(kt * 8 + q + p * 4) * 256 + G]);
    }

    for (int i = tid; i < 2 * 16 * 68; i += 256) hbuf[i] = 0.f;

    const int rowsel = ((lane & 16) >> 1) + (lane & 7);
    const int colsel = ((lane >> 3) & 1) * 4;
    const uint32_t hbase = smem_u32(hbuf);
    const uint32_t xbase = smem_u32(sxg);
    const bool isState = (lane & 1);
    const int g0 = (q & 1) * 2;
    int colA[4], hj[4];
    #pragma unroll
    for (int nt = 0; nt < 4; ++nt) {
        int a_local = w * 8 + nt * 2 + (q >> 1);
        colA[nt] = g0 * 64 + a_local;
        hj[nt]   = a_local;
    }
    const int r = lane >> 2;

    float cst[4][2];
    #pragma unroll
    for (int nt = 0; nt < 4; ++nt) { cst[nt][0] = 0.f; cst[nt][1] = 0.f; }

    auto issue_xg = [&](int tt, int stage) {
        const uint32_t dst0 = xbase + (uint32_t)(stage * 16 * XS2 * 4);
        #pragma unroll
        for (int i = 0; i < 4; ++i) {
            int idx = tid + i * 256;
            int row = idx >> 6, c4 = idx & 63;
            CP_ASYNC16(dst0 + (uint32_t)((row * XS2 + c4 * 4) * 4),
                       xg + ((size_t)(b0 + row) * 512 + tt) * 256 + c4 * 4);
        }
        CP_COMMIT();
    };

    __syncthreads();
    issue_xg(dir ? 511 : 0, 0);

    for (int t = 0; t < 512; ++t) {
        const int tt  = dir ? (511 - t) : t;
        const int cur = t & 1, nxt = cur ^ 1;

        if (t + 1 < 512) { issue_xg(dir ? (510 - t) : (t + 1), nxt); CP_WAIT(1); }
        else             { CP_WAIT(0); }
        __syncthreads();

        const float* xs = sxg + cur * 16 * XS2;
        float acc[4][4];
        #pragma unroll
        for (int nt = 0; nt < 4; ++nt) {
            acc[nt][0] = xs[r * XS2 + colA[nt]];
            acc[nt][1] = xs[r * XS2 + colA[nt] + 64];
            acc[nt][2] = xs[(r + 8) * XS2 + colA[nt]];
            acc[nt][3] = xs[(r + 8) * XS2 + colA[nt] + 64];
        }

        const uint32_t abase = hbase + (uint32_t)(cur * 16 * 68 * 4);
        #pragma unroll
        for (int kt = 0; kt < 8; ++kt) {
            uint32_t a0, a1, a2, a3;
            LDMATRIX_X4(a0, a2, a1, a3,
                        abase + (uint32_t)((rowsel * 68 + kt * 8 + colsel) * 4));
            uint32_t afr[4] = {a0, a1, a2, a3};
            #pragma unroll
            for (int nt = 0; nt < 4; ++nt)
                mma_tf32(acc[nt], afr, bfr[nt][kt]);
        }

        #pragma unroll
        for (int nt = 0; nt < 4; ++nt) {
            float v0 = isState ? fmaxf(acc[nt][0], 0.f) : sigf(acc[nt][0]);
            float v1 = sigf(acc[nt][1]);
            float v2 = isState ? fmaxf(acc[nt][2], 0.f) : sigf(acc[nt][2]);
            float v3 = sigf(acc[nt][3]);
            float s0 = __shfl_xor_sync(0xffffffffu, v0, 1);
            float s1 = __shfl_xor_sync(0xffffffffu, v1, 1);
            float s2 = __shfl_xor_sync(0xffffffffu, v2, 1);
            float s3 = __shfl_xor_sync(0xffffffffu, v3, 1);
            if (isState) {
                float c0 = s1 * cst[nt][0] + s0 * v0;
                float c1 = s3 * cst[nt][1] + s2 * v2;
                cst[nt][0] = c0; cst[nt][1] = c1;
                float h0 = v1 * fmaxf(c0, 0.f);
                float h1 = v3 * fmaxf(c1, 0.f);
                hbuf[nxt * 16 * 68 + r * 68 + hj[nt]]       = __uint_as_float(f2tf32(h0));
                hbuf[nxt * 16 * 68 + (r + 8) * 68 + hj[nt]] = __uint_as_float(f2tf32(h1));
                if (t == 511) {
                    hout[(size_t)(b0 + r) * 128 + dir * 64 + hj[nt]]     = h0;
                    hout[(size_t)(b0 + r + 8) * 128 + dir * 64 + hj[nt]] = h1;
                }
            }
        }
        __syncthreads();
    }
}

// ------------------------------ heads ---------------------------------------
__global__ void __launch_bounds__(256)
head_kernel(const float* __restrict__ x64, const float* __restrict__ h2,
            const float* __restrict__ wz1, const float* __restrict__ bz1,
            const float* __restrict__ wz2, const float* __restrict__ bz2,
            const float* __restrict__ wt1, const float* __restrict__ bt1,
            const float* __restrict__ wt2, const float* __restrict__ bt2,
            float* __restrict__ out)
{
    const int b = threadIdx.x;
    float comb[192];
    #pragma unroll 4
    for (int k = 0; k < 64; ++k)  comb[k]      = x64[b*64 + k];
    #pragma unroll 4
    for (int k = 0; k < 128; ++k) comb[64 + k] = h2[b*128 + k];

    float z0 = bz1[0], z1 = bz1[1], t0 = bt1[0], t1 = bt1[1];
    #pragma unroll 4
    for (int k = 0; k < 192; ++k) {
        float v = comb[k];
        z0 += v * wz1[k*2 + 0]; z1 += v * wz1[k*2 + 1];
        t0 += v * wt1[k*2 + 0]; t1 += v * wt1[k*2 + 1];
    }
    out[b]       = fmaxf(z0,0.f)*wz2[0] + fmaxf(z1,0.f)*wz2[1] + bz2[0];
    out[256 + b] = fmaxf(t0,0.f)*wt2[0] + fmaxf(t1,0.f)*wt2[1] + bt2[0];
}

// ------------------------------ launcher ------------------------------------
extern "C" void kernel_launch(void* const* d_in, const int* in_sizes, int n_in,
                              void* d_out, int out_size)
{
    const int*   inputA = (const int*)  d_in[0];
    const float* inputB = (const float*)d_in[1];
    const float* emb = (const float*)d_in[2];
    const float *w1=(const float*)d_in[3],  *b1=(const float*)d_in[4];
    const float *w2=(const float*)d_in[5],  *b2=(const float*)d_in[6];
    const float *w3=(const float*)d_in[7],  *b3=(const float*)d_in[8];
    const float *k1f=(const float*)d_in[9],  *r1f=(const float*)d_in[10], *bb1f=(const float*)d_in[11];
    const float *k1b=(const float*)d_in[12], *r1b=(const float*)d_in[13], *bb1b=(const float*)d_in[14];
    const float *k2f=(const float*)d_in[15], *r2f=(const float*)d_in[16], *bb2f=(const float*)d_in[17];
    const float *k2b=(const float*)d_in[18], *r2b=(const float*)d_in[19], *bb2b=(const float*)d_in[20];
    const float *wz1=(const float*)d_in[21], *bz1=(const float*)d_in[22];
    const float *wz2=(const float*)d_in[23], *bz2=(const float*)d_in[24];
    const float *wt1=(const float*)d_in[25], *bt1=(const float*)d_in[26];
    const float *wt2=(const float*)d_in[27], *bt2=(const float*)d_in[28];
    float* out = (float*)d_out;

    float *xg1f, *xg1b, *xg2f, *xg2b, *x64, *h2;
    __nv_bfloat16 *xBhi, *xBlo, *Yhi, *Ylo, *wThi, *wTlo;
    cudaGetSymbolAddress((void**)&xg1f, g_xg1f);
    cudaGetSymbolAddress((void**)&xg1b, g_xg1b);
    cudaGetSymbolAddress((void**)&xg2f, g_xg2f);
    cudaGetSymbolAddress((void**)&xg2b, g_xg2b);
    cudaGetSymbolAddress((void**)&x64,  g_x64);
    cudaGetSymbolAddress((void**)&h2,   g_h2);
    cudaGetSymbolAddress((void**)&xBhi, g_xBhi);
    cudaGetSymbolAddress((void**)&xBlo, g_xBlo);
    cudaGetSymbolAddress((void**)&Yhi,  g_Yhi);
    cudaGetSymbolAddress((void**)&Ylo,  g_Ylo);
    cudaGetSymbolAddress((void**)&wThi, g_wThi);
    cudaGetSymbolAddress((void**)&wTlo, g_wTlo);

    __nv_bfloat16 *w1fh = wThi,            *w1fl = wTlo;
    __nv_bfloat16 *w1bh = wThi + 65536,    *w1bl = wTlo + 65536;
    __nv_bfloat16 *w2fh = wThi + 2*65536,  *w2fl = wTlo + 2*65536;
    __nv_bfloat16 *w2bh = wThi + 3*65536,  *w2bl = wTlo + 3*65536;

    const size_t sm1 = (size_t)(2*16*XS1 + 2*16*132 + 16*68) * sizeof(float);
    const size_t sm2 = (size_t)(2*16*XS2 + 2*16*68) * sizeof(float);

    static bool attr_done = false;
    if (!attr_done) {
        cudaFuncSetAttribute(gemm_bf16_kernel, cudaFuncAttributeMaxDynamicSharedMemorySize, 2*GSTAGE);
        cudaFuncSetAttribute(lstm1_mma_kernel, cudaFuncAttributeMaxDynamicSharedMemorySize, (int)sm1);
        cudaFuncSetAttribute(lstm2_mma_kernel, cudaFuncAttributeMaxDynamicSharedMemorySize, (int)sm2);
        attr_done = true;
    }

    // prep: split inputB, transpose+split weights
    split_kernel<<<(BT*128/4 + 255)/256, 256>>>(inputB, xBhi, xBlo, BT*128/4);
    transpose_split_kernel<<<(65536+255)/256, 256>>>(k1f, w1fh, w1fl, 128, 512);
    transpose_split_kernel<<<(65536+255)/256, 256>>>(k1b, w1bh, w1bl, 128, 512);
    transpose_split_kernel<<<(65536+255)/256, 256>>>(k2f, w2fh, w2fl, 256, 256);
    transpose_split_kernel<<<(65536+255)/256, 256>>>(k2b, w2bh, w2bl, 256, 256);

    emb_mlp_kernel<<<256, 256>>>(inputA, emb, w1,b1, w2,b2, w3,b3, x64);

    const size_t gsm = 2*GSTAGE;
    gemm_bf16_kernel<<<dim3(1024,4), 256, gsm>>>(xBhi, xBlo, w1fh, w1fl, bb1f, xg1f, BT, 512, 128);
    gemm_bf16_kernel<<<dim3(1024,4), 256, gsm>>>(xBhi, xBlo, w1bh, w1bl, bb1b, xg1b, BT, 512, 128);

    lstm1_mma_kernel<<<dim3(32,2), 256, sm1>>>(xg1f, xg1b, r1f, r1b, Yhi, Ylo);

    gemm_bf16_kernel<<<dim3(1024,2), 256, gsm>>>(Yhi, Ylo, w2fh, w2fl, bb2f, xg2f, BT, 256, 256);
    gemm_bf16_kernel<<<dim3(1024,2), 256, gsm>>>(Yhi, Ylo, w2bh, w2bl, bb2b, xg2b, BT, 256, 256);

    lstm2_mma_kernel<<<dim3(16,2), 256, sm2>>>(xg2f, xg2b, r2f, r2b, h2);

    head_kernel<<<1, 256>>>(x64, h2, wz1,bz1, wz2,bz2, wt1,bt1, wt2,bt2, out);
}

// round 10
// speedup vs baseline: 1.6436x; 1.1740x over previous
#include <cuda_runtime.h>
#include <cuda_fp16.h>
#include <cooperative_groups.h>
#include <cstdint>
namespace cg = cooperative_groups;

// ------------------------- scratch (device globals) -------------------------
#define BT (256*512)
__device__ float g_x64 [256*64];
__device__ float g_xg1f[(size_t)BT*512];
__device__ float g_xg1b[(size_t)BT*512];
__device__ float g_xg2f[(size_t)BT*256];
__device__ float g_xg2b[(size_t)BT*256];
__device__ float g_h2  [256*128];
__device__ __half g_xBhi[(size_t)BT*128];
__device__ __half g_xBlo[(size_t)BT*128];
__device__ __half g_Yhi [(size_t)BT*256];
__device__ __half g_Ylo [(size_t)BT*256];
__device__ __half g_wTh [4*65536];          // transposed weights [N,K], fp16

// ------------------------- small PTX helpers --------------------------------
__device__ __forceinline__ uint32_t smem_u32(const void* p) {
    uint32_t a;
    asm("{ .reg .u64 t; cvta.to.shared.u64 t, %1; cvt.u32.u64 %0, t; }" : "=r"(a) : "l"(p));
    return a;
}
__device__ __forceinline__ void mma_fp16(float* c, const uint32_t* a, const uint32_t* b) {
    asm volatile("mma.sync.aligned.m16n8k16.row.col.f32.f16.f16.f32 "
        "{%0,%1,%2,%3},{%4,%5,%6,%7},{%8,%9},{%0,%1,%2,%3};"
        : "+f"(c[0]), "+f"(c[1]), "+f"(c[2]), "+f"(c[3])
        : "r"(a[0]), "r"(a[1]), "r"(a[2]), "r"(a[3]), "r"(b[0]), "r"(b[1]));
}
#define LDMATRIX_X4(r0, r1, r2, r3, addr) \
    asm volatile("ldmatrix.sync.aligned.m8n8.x4.shared.b16 {%0,%1,%2,%3}, [%4];" \
        : "=r"(r0), "=r"(r1), "=r"(r2), "=r"(r3) : "r"(addr))
#define CP_ASYNC16(dst, src) asm volatile("cp.async.cg.shared.global [%0], [%1], 16;" :: "r"(dst), "l"(src))
#define CP_COMMIT()          asm volatile("cp.async.commit_group;" ::: "memory")
#define CP_WAIT(n)           asm volatile("cp.async.wait_group %0;" :: "n"(n) : "memory")

__device__ __forceinline__ float sigf(float x) {
    return 1.f / (1.f + __expf(-x));
}
__device__ __forceinline__ uint32_t pack_h2(__half a, __half b) {
    __half2 t = __halves2half2(a, b);
    return *(uint32_t*)&t;
}
__device__ __forceinline__ void split_h(float f, __half& hi, __half& lo) {
    hi = __float2half(f);
    lo = __float2half(f - __half2float(hi));
}

// ------------------- prep: fp16 split / transpose+round ---------------------
__global__ void __launch_bounds__(256)
split_fp16_kernel(const float* __restrict__ in, __half* __restrict__ hi,
                  __half* __restrict__ lo, int n4)
{
    int i = blockIdx.x * 256 + threadIdx.x;
    if (i < n4) {
        float4 v = ((const float4*)in)[i];
        __half h0,h1,h2,h3,l0,l1,l2,l3;
        split_h(v.x,h0,l0); split_h(v.y,h1,l1);
        split_h(v.z,h2,l2); split_h(v.w,h3,l3);
        ((uint2*)hi)[i] = make_uint2(pack_h2(h0,h1), pack_h2(h2,h3));
        ((uint2*)lo)[i] = make_uint2(pack_h2(l0,l1), pack_h2(l2,l3));
    }
}
__global__ void __launch_bounds__(256)
transpose_fp16_kernel(const float* __restrict__ in, __half* __restrict__ out, int K, int N)
{
    int idx = blockIdx.x * 256 + threadIdx.x;
    if (idx < K * N) {
        int n = idx / K, k = idx - n * K;
        out[idx] = __float2half(in[k * N + n]);
    }
}

// ---- fp16 asymmetric 2-product GEMM + bias: C = (Ahi+Alo) @ W^T + b --------
// A pre-split fp16 hi/lo (near-exact); W single fp16 (only rounding source).
// Block 128x128, BK=32, 2-stage cp.async, 8 warps (2m x 4n), warp tile 64x32.
// SMEM stage: Ahi/Alo/W each 128 rows x 40 fp16 (80B stride) = 10240B.
#define GSTAGE 30720
__global__ void __launch_bounds__(256, 2)
gemm_fp16_kernel(const __half* __restrict__ Ahi, const __half* __restrict__ Alo,
                 const __half* __restrict__ W,
                 const float* __restrict__ bias, float* __restrict__ C,
                 int M, int N, int K)
{
    extern __shared__ char smem[];
    const uint32_t smem_base = smem_u32(smem);
    const int tid = threadIdx.x;
    const int lane = tid & 31, wid = tid >> 5;
    const int m0 = blockIdx.x * 128, n0 = blockIdx.y * 128;
    const int wm = (wid >> 2) * 64, wn = (wid & 3) * 32;

    float acc[4][4][4];
    #pragma unroll
    for (int mt = 0; mt < 4; ++mt)
        #pragma unroll
        for (int nt = 0; nt < 4; ++nt)
            #pragma unroll
            for (int q = 0; q < 4; ++q) acc[mt][nt][q] = 0.f;

    const uint32_t lrow = (uint32_t)(lane & 15);
    const uint32_t lcol = (uint32_t)((lane >> 4) * 16);
    uint32_t offA[4], offB[2];
    #pragma unroll
    for (int mt = 0; mt < 4; ++mt)
        offA[mt] = (uint32_t)(wm + mt * 16 + lrow) * 80u + lcol;
    #pragma unroll
    for (int p = 0; p < 2; ++p)
        offB[p] = (uint32_t)(wn + p * 16 + lrow) * 80u + lcol;

    const int nch = K >> 5;
    auto issue = [&](int ch, int stage) {
        const int kc = ch << 5;
        const uint32_t st = smem_base + (uint32_t)stage * GSTAGE;
        #pragma unroll
        for (int i = 0; i < 2; ++i) {
            int idx = tid + i * 256;                 // 0..511
            int row = idx >> 2, c = idx & 3;         // 128 rows x 4 x 16B
            uint32_t soff = (uint32_t)(row * 80 + c * 16);
            size_t ga = (size_t)(m0 + row) * K + kc + c * 8;
            size_t gb = (size_t)(n0 + row) * K + kc + c * 8;
            CP_ASYNC16(st + soff,           Ahi + ga);
            CP_ASYNC16(st + 10240u + soff,  Alo + ga);
            CP_ASYNC16(st + 20480u + soff,  W   + gb);
        }
        CP_COMMIT();
    };

    issue(0, 0);
    for (int ch = 0; ch < nch; ++ch) {
        if (ch + 1 < nch) { issue(ch + 1, (ch + 1) & 1); CP_WAIT(1); }
        else             { CP_WAIT(0); }
        __syncthreads();

        const uint32_t stg = smem_base + (uint32_t)(ch & 1) * GSTAGE;
        #pragma unroll
        for (int kk = 0; kk < 2; ++kk) {             // two k16 steps per chunk
            const uint32_t kb = (uint32_t)(kk * 32); // 16 fp16 = 32B

            uint32_t bfr[4][2];
            #pragma unroll
            for (int p = 0; p < 2; ++p) {
                uint32_t r0, r1, r2, r3;
                LDMATRIX_X4(r0, r1, r2, r3, stg + 20480u + offB[p] + kb);
                bfr[2*p][0] = r0; bfr[2*p+1][0] = r1;
                bfr[2*p][1] = r2; bfr[2*p+1][1] = r3;
            }

            #pragma unroll
            for (int mt = 0; mt < 4; ++mt) {
                uint32_t ahi[4], alo[4];
                LDMATRIX_X4(ahi[0], ahi[1], ahi[2], ahi[3], stg + offA[mt] + kb);
                LDMATRIX_X4(alo[0], alo[1], alo[2], alo[3], stg + 10240u + offA[mt] + kb);
                #pragma unroll
                for (int nt = 0; nt < 4; ++nt) {
                    mma_fp16(acc[mt][nt], ahi, bfr[nt]);
                    mma_fp16(acc[mt][nt], alo, bfr[nt]);
                }
            }
        }
        __syncthreads();
    }

    #pragma unroll
    for (int mt = 0; mt < 4; ++mt) {
        int r = m0 + wm + mt * 16 + (lane >> 2);
        #pragma unroll
        for (int nt = 0; nt < 4; ++nt) {
            int col = n0 + wn + nt * 8 + (lane & 3) * 2;
            float b0 = __ldg(bias + col), b1 = __ldg(bias + col + 1);
            float2 v0 = make_float2(acc[mt][nt][0] + b0, acc[mt][nt][1] + b1);
            float2 v1 = make_float2(acc[mt][nt][2] + b0, acc[mt][nt][3] + b1);
            *(float2*)(C + (size_t)r * N + col)       = v0;
            *(float2*)(C + (size_t)(r + 8) * N + col) = v1;
        }
    }
}

// ------------------------- embedding MLP branch -----------------------------
__global__ void __launch_bounds__(256)
emb_mlp_kernel(const int* __restrict__ inputA, const float* __restrict__ emb,
               const float* __restrict__ w1, const float* __restrict__ b1,
               const float* __restrict__ w2, const float* __restrict__ b2,
               const float* __restrict__ w3, const float* __restrict__ b3,
               float* __restrict__ xout)
{
    __shared__ float x0[600], x1[256], x2[128];
    const int b = blockIdx.x, tid = threadIdx.x;
    for (int i = tid; i < 600; i += 256) {
        int la = i / 3, comp = i - la * 3;
        x0[i] = emb[inputA[b*200 + la]*3 + comp];
    }
    __syncthreads();
    {
        float acc = b1[tid];
        #pragma unroll 4
        for (int k = 0; k < 600; ++k) acc += x0[k] * w1[k*256 + tid];
        x1[tid] = fmaxf(acc, 0.f);
    }
    __syncthreads();
    if (tid < 128) {
        float acc = b2[tid];
        #pragma unroll 4
        for (int k = 0; k < 256; ++k) acc += x1[k] * w2[k*128 + tid];
        x2[tid] = fmaxf(acc, 0.f);
    }
    __syncthreads();
    if (tid < 64) {
        float acc = b3[tid];
        #pragma unroll 4
        for (int k = 0; k < 128; ++k) acc += x2[k] * w3[k*64 + tid];
        xout[b*64 + tid] = fmaxf(acc, 0.f);
    }
}

// ------------- LSTM layer 1 (H=128) — fp16-k16 tensor-core recurrence -------
// Same structure as R7/R8 (verified), but weight frags + h buffers in fp16
// (same 2^-11 rounding class as tf32) -> half the HMMA and ldmatrix per step.
#define XS1 516
#define HS1 136                 // hbuf row stride in halves (272B = 17*16B)
__global__ void __cluster_dims__(2,1,1) __launch_bounds__(256, 1)
lstm1_mma_kernel(const float* __restrict__ xg1f, const float* __restrict__ xg1b,
                 const float* __restrict__ r1f,  const float* __restrict__ r1b,
                 __half* __restrict__ Yhi, __half* __restrict__ Ylo)
{
    extern __shared__ char smraw[];
    float*  sxg   = (float*)smraw;                              // 2*16*XS1 f32
    __half* hbufh = (__half*)(smraw + 2*16*XS1*4);              // 2*16*HS1 f16
    float*  ybuf  = (float*)(smraw + 2*16*XS1*4 + 2*16*HS1*2);  // 16*68 f32

    cg::cluster_group cl = cg::this_cluster();
    const int rank = cl.block_rank();
    const int dir  = blockIdx.y;
    const int b0   = (blockIdx.x >> 1) * 16;
    const int tid  = threadIdx.x;
    const int lane = tid & 31, w = tid >> 5;
    const int q    = lane & 3;
    const float* xg = dir ? xg1b : xg1f;
    const float* Wr = dir ? r1b : r1f;

    // fp16 weight fragments (k16), packed pairs: low half = even k
    uint32_t bfr[4][8][2];
    #pragma unroll
    for (int nt = 0; nt < 4; ++nt) {
        int n_local = w * 32 + nt * 8 + (lane >> 2);
        int G = (n_local & 3) * 128 + rank * 64 + (n_local >> 2);
        #pragma unroll
        for (int kt = 0; kt < 8; ++kt)
            #pragma unroll
            for (int p = 0; p < 2; ++p) {
                int k = kt * 16 + q * 2 + p * 8;
                bfr[nt][kt][p] = pack_h2(__float2half(Wr[k * 512 + G]),
                                         __float2half(Wr[(k + 1) * 512 + G]));
            }
    }

    for (int i = tid; i < 2 * 16 * HS1; i += 256) hbufh[i] = __float2half(0.f);

    const uint32_t hb32 = smem_u32(hbufh);
    const uint32_t xbase = smem_u32(sxg);
    // ldmatrix b16 lane addressing on 16x16 fp16 tiles
    const uint32_t lmbase = (uint32_t)(((lane & 15) * HS1 + ((lane >> 4) << 3)) * 2);
    const bool isState = (lane & 1);
    const int g0 = (q & 1) * 2;
    int colA[4], hj[4], al[4];
    #pragma unroll
    for (int nt = 0; nt < 4; ++nt) {
        int a_local = w * 8 + nt * 2 + (q >> 1);
        colA[nt] = g0 * 128 + rank * 64 + a_local;
        hj[nt]   = rank * 64 + a_local;
        al[nt]   = a_local;
    }
    const int r = lane >> 2;

    float cst[4][2];
    #pragma unroll
    for (int nt = 0; nt < 4; ++nt) { cst[nt][0] = 0.f; cst[nt][1] = 0.f; }

    auto issue_xg = [&](int tt, int stage) {
        const uint32_t dst0 = xbase + (uint32_t)(stage * 16 * XS1 * 4);
        #pragma unroll
        for (int i = 0; i < 8; ++i) {
            int idx = tid + i * 256;
            int row = idx >> 7, c4 = idx & 127;
            CP_ASYNC16(dst0 + (uint32_t)((row * XS1 + c4 * 4) * 4),
                       xg + ((size_t)(b0 + row) * 512 + tt) * 512 + c4 * 4);
        }
        CP_COMMIT();
    };

    __half* peer_h = (__half*)cl.map_shared_rank((void*)hbufh, rank ^ 1);
    __syncthreads();
    cl.sync();

    issue_xg(dir ? 511 : 0, 0);

    for (int t = 0; t < 512; ++t) {
        const int tt  = dir ? (511 - t) : t;
        const int cur = t & 1, nxt = cur ^ 1;

        if (t + 1 < 512) { issue_xg(dir ? (510 - t) : (t + 1), nxt); CP_WAIT(1); }
        else             { CP_WAIT(0); }
        __syncthreads();

        const float* xs = sxg + cur * 16 * XS1;
        float acc[4][4];
        #pragma unroll
        for (int nt = 0; nt < 4; ++nt) {
            acc[nt][0] = xs[r * XS1 + colA[nt]];
            acc[nt][1] = xs[r * XS1 + colA[nt] + 128];
            acc[nt][2] = xs[(r + 8) * XS1 + colA[nt]];
            acc[nt][3] = xs[(r + 8) * XS1 + colA[nt] + 128];
        }

        // h @ Wr via fp16 k16 mma: 8 ldmatrix + 32 HMMA per warp
        const uint32_t abase = hb32 + (uint32_t)(cur * 16 * HS1 * 2) + lmbase;
        #pragma unroll
        for (int kt = 0; kt < 8; ++kt) {
            uint32_t a0, a1, a2, a3;
            LDMATRIX_X4(a0, a1, a2, a3, abase + (uint32_t)(kt * 32));
            uint32_t afr[4] = {a0, a1, a2, a3};
            #pragma unroll
            for (int nt = 0; nt < 4; ++nt)
                mma_fp16(acc[nt], afr, bfr[nt][kt]);
        }

        #pragma unroll
        for (int nt = 0; nt < 4; ++nt) {
            float v0 = isState ? fmaxf(acc[nt][0], 0.f) : sigf(acc[nt][0]);
            float v1 = sigf(acc[nt][1]);
            float v2 = isState ? fmaxf(acc[nt][2], 0.f) : sigf(acc[nt][2]);
            float v3 = sigf(acc[nt][3]);
            float s0 = __shfl_xor_sync(0xffffffffu, v0, 1);
            float s1 = __shfl_xor_sync(0xffffffffu, v1, 1);
            float s2 = __shfl_xor_sync(0xffffffffu, v2, 1);
            float s3 = __shfl_xor_sync(0xffffffffu, v3, 1);
            if (isState) {
                float c0 = s1 * cst[nt][0] + s0 * v0;
                float c1 = s3 * cst[nt][1] + s2 * v2;
                cst[nt][0] = c0; cst[nt][1] = c1;
                float h0 = v1 * fmaxf(c0, 0.f);
                float h1 = v3 * fmaxf(c1, 0.f);
                __half h0h = __float2half(h0);
                __half h1h = __float2half(h1);
                int o0 = nxt * 16 * HS1 + r * HS1 + hj[nt];
                int o1 = nxt * 16 * HS1 + (r + 8) * HS1 + hj[nt];
                hbufh[o0] = h0h;  hbufh[o1] = h1h;
                peer_h[o0] = h0h; peer_h[o1] = h1h;
                ybuf[r * 68 + al[nt]]       = h0;
                ybuf[(r + 8) * 68 + al[nt]] = h1;
            }
        }
        cl.sync();

        // coalesced Y store: own 64-col slice, split to fp16 hi/lo
        {
            int row = tid >> 4, c4 = tid & 15;
            float4 v = *(const float4*)&ybuf[row * 68 + c4 * 4];
            size_t idx = ((size_t)(b0 + row) * 512 + tt) * 256
                         + dir * 128 + rank * 64 + c4 * 4;
            __half h0,h1,h2,h3,l0,l1,l2,l3;
            split_h(v.x,h0,l0); split_h(v.y,h1,l1);
            split_h(v.z,h2,l2); split_h(v.w,h3,l3);
            *(uint2*)&Yhi[idx] = make_uint2(pack_h2(h0,h1), pack_h2(h2,h3));
            *(uint2*)&Ylo[idx] = make_uint2(pack_h2(l0,l1), pack_h2(l2,l3));
        }
    }
}

// ------------- LSTM layer 2 (H=64) — fp16-k16 tensor-core recurrence --------
#define XS2 260
#define HS2 72                  // hbuf row stride in halves (144B = 9*16B)
__global__ void __launch_bounds__(256, 1)
lstm2_mma_kernel(const float* __restrict__ xg2f, const float* __restrict__ xg2b,
                 const float* __restrict__ r2f,  const float* __restrict__ r2b,
                 float* __restrict__ hout)
{
    extern __shared__ char smraw[];
    float*  sxg   = (float*)smraw;                     // 2*16*XS2 f32
    __half* hbufh = (__half*)(smraw + 2*16*XS2*4);     // 2*16*HS2 f16

    const int dir = blockIdx.y;
    const int b0  = blockIdx.x * 16;
    const int tid = threadIdx.x;
    const int lane = tid & 31, w = tid >> 5;
    const int q = lane & 3;
    const float* xg = dir ? xg2b : xg2f;
    const float* Wr = dir ? r2b : r2f;

    uint32_t bfr[4][4][2];
    #pragma unroll
    for (int nt = 0; nt < 4; ++nt) {
        int n_local = w * 32 + nt * 8 + (lane >> 2);
        int G = (n_local & 3) * 64 + (n_local >> 2);
        #pragma unroll
        for (int kt = 0; kt < 4; ++kt)
            #pragma unroll
            for (int p = 0; p < 2; ++p) {
                int k = kt * 16 + q * 2 + p * 8;
                bfr[nt][kt][p] = pack_h2(__float2half(Wr[k * 256 + G]),
                                         __float2half(Wr[(k + 1) * 256 + G]));
            }
    }

    for (int i = tid; i < 2 * 16 * HS2; i += 256) hbufh[i] = __float2half(0.f);

    const uint32_t hb32 = smem_u32(hbufh);
    const uint32_t xbase = smem_u32(sxg);
    const uint32_t lmbase = (uint32_t)(((lane & 15) * HS2 + ((lane >> 4) << 3)) * 2);
    const bool isState = (lane & 1);
    const int g0 = (q & 1) * 2;
    int colA[4], hj[4];
    #pragma unroll
    for (int nt = 0; nt < 4; ++nt) {
        int a_local = w * 8 + nt * 2 + (q >> 1);
        colA[nt] = g0 * 64 + a_local;
        hj[nt]   = a_local;
    }
    const int r = lane >> 2;

    float cst[4][2];
    #pragma unroll
    for (int nt = 0; nt < 4; ++nt) { cst[nt][0] = 0.f; cst[nt][1] = 0.f; }

    auto issue_xg = [&](int tt, int stage) {
        const uint32_t dst0 = xbase + (uint32_t)(stage * 16 * XS2 * 4);
        #pragma unroll
        for (int i = 0; i < 4; ++i) {
            int idx = tid + i * 256;
            int row = idx >> 6, c4 = idx & 63;
            CP_ASYNC16(dst0 + (uint32_t)((row * XS2 + c4 * 4) * 4),
                       xg + ((size_t)(b0 + row) * 512 + tt) * 256 + c4 * 4);
        }
        CP_COMMIT();
    };

    __syncthreads();
    issue_xg(dir ? 511 : 0, 0);

    for (int t = 0; t < 512; ++t) {
        const int tt  = dir ? (511 - t) : t;
        const int cur = t & 1, nxt = cur ^ 1;

        if (t + 1 < 512) { issue_xg(dir ? (510 - t) : (t + 1), nxt); CP_WAIT(1); }
        else             { CP_WAIT(0); }
        __syncthreads();

        const float* xs = sxg + cur * 16 * XS2;
        float acc[4][4];
        #pragma unroll
        for (int nt = 0; nt < 4; ++nt) {
            acc[nt][0] = xs[r * XS2 + colA[nt]];
            acc[nt][1] = xs[r * XS2 + colA[nt] + 64];
            acc[nt][2] = xs[(r + 8) * XS2 + colA[nt]];
            acc[nt][3] = xs[(r + 8) * XS2 + colA[nt] + 64];
        }

        const uint32_t abase = hb32 + (uint32_t)(cur * 16 * HS2 * 2) + lmbase;
        #pragma unroll
        for (int kt = 0; kt < 4; ++kt) {
            uint32_t a0, a1, a2, a3;
            LDMATRIX_X4(a0, a1, a2, a3, abase + (uint32_t)(kt * 32));
            uint32_t afr[4] = {a0, a1, a2, a3};
            #pragma unroll
            for (int nt = 0; nt < 4; ++nt)
                mma_fp16(acc[nt], afr, bfr[nt][kt]);
        }

        #pragma unroll
        for (int nt = 0; nt < 4; ++nt) {
            float v0 = isState ? fmaxf(acc[nt][0], 0.f) : sigf(acc[nt][0]);
            float v1 = sigf(acc[nt][1]);
            float v2 = isState ? fmaxf(acc[nt][2], 0.f) : sigf(acc[nt][2]);
            float v3 = sigf(acc[nt][3]);
            float s0 = __shfl_xor_sync(0xffffffffu, v0, 1);
            float s1 = __shfl_xor_sync(0xffffffffu, v1, 1);
            float s2 = __shfl_xor_sync(0xffffffffu, v2, 1);
            float s3 = __shfl_xor_sync(0xffffffffu, v3, 1);
            if (isState) {
                float c0 = s1 * cst[nt][0] + s0 * v0;
                float c1 = s3 * cst[nt][1] + s2 * v2;
                cst[nt][0] = c0; cst[nt][1] = c1;
                float h0 = v1 * fmaxf(c0, 0.f);
                float h1 = v3 * fmaxf(c1, 0.f);
                hbufh[nxt * 16 * HS2 + r * HS2 + hj[nt]]       = __float2half(h0);
                hbufh[nxt * 16 * HS2 + (r + 8) * HS2 + hj[nt]] = __float2half(h1);
                if (t == 511) {
                    hout[(size_t)(b0 + r) * 128 + dir * 64 + hj[nt]]     = h0;
                    hout[(size_t)(b0 + r + 8) * 128 + dir * 64 + hj[nt]] = h1;
                }
            }
        }
        __syncthreads();
    }
}

// ------------------------------ heads ---------------------------------------
__global__ void __launch_bounds__(256)
head_kernel(const float* __restrict__ x64, const float* __restrict__ h2,
            const float* __restrict__ wz1, const float* __restrict__ bz1,
            const float* __restrict__ wz2, const float* __restrict__ bz2,
            const float* __restrict__ wt1, const float* __restrict__ bt1,
            const float* __restrict__ wt2, const float* __restrict__ bt2,
            float* __restrict__ out)
{
    const int b = threadIdx.x;
    float comb[192];
    #pragma unroll 4
    for (int k = 0; k < 64; ++k)  comb[k]      = x64[b*64 + k];
    #pragma unroll 4
    for (int k = 0; k < 128; ++k) comb[64 + k] = h2[b*128 + k];

    float z0 = bz1[0], z1 = bz1[1], t0 = bt1[0], t1 = bt1[1];
    #pragma unroll 4
    for (int k = 0; k < 192; ++k) {
        float v = comb[k];
        z0 += v * wz1[k*2 + 0]; z1 += v * wz1[k*2 + 1];
        t0 += v * wt1[k*2 + 0]; t1 += v * wt1[k*2 + 1];
    }
    out[b]       = fmaxf(z0,0.f)*wz2[0] + fmaxf(z1,0.f)*wz2[1] + bz2[0];
    out[256 + b] = fmaxf(t0,0.f)*wt2[0] + fmaxf(t1,0.f)*wt2[1] + bt2[0];
}

// ------------------------------ launcher ------------------------------------
extern "C" void kernel_launch(void* const* d_in, const int* in_sizes, int n_in,
                              void* d_out, int out_size)
{
    const int*   inputA = (const int*)  d_in[0];
    const float* inputB = (const float*)d_in[1];
    const float* emb = (const float*)d_in[2];
    const float *w1=(const float*)d_in[3],  *b1=(const float*)d_in[4];
    const float *w2=(const float*)d_in[5],  *b2=(const float*)d_in[6];
    const float *w3=(const float*)d_in[7],  *b3=(const float*)d_in[8];
    const float *k1f=(const float*)d_in[9],  *r1f=(const float*)d_in[10], *bb1f=(const float*)d_in[11];
    const float *k1b=(const float*)d_in[12], *r1b=(const float*)d_in[13], *bb1b=(const float*)d_in[14];
    const float *k2f=(const float*)d_in[15], *r2f=(const float*)d_in[16], *bb2f=(const float*)d_in[17];
    const float *k2b=(const float*)d_in[18], *r2b=(const float*)d_in[19], *bb2b=(const float*)d_in[20];
    const float *wz1=(const float*)d_in[21], *bz1=(const float*)d_in[22];
    const float *wz2=(const float*)d_in[23], *bz2=(const float*)d_in[24];
    const float *wt1=(const float*)d_in[25], *bt1=(const float*)d_in[26];
    const float *wt2=(const float*)d_in[27], *bt2=(const float*)d_in[28];
    float* out = (float*)d_out;

    float *xg1f, *xg1b, *xg2f, *xg2b, *x64, *h2;
    __half *xBhi, *xBlo, *Yhi, *Ylo, *wTh;
    cudaGetSymbolAddress((void**)&xg1f, g_xg1f);
    cudaGetSymbolAddress((void**)&xg1b, g_xg1b);
    cudaGetSymbolAddress((void**)&xg2f, g_xg2f);
    cudaGetSymbolAddress((void**)&xg2b, g_xg2b);
    cudaGetSymbolAddress((void**)&x64,  g_x64);
    cudaGetSymbolAddress((void**)&h2,   g_h2);
    cudaGetSymbolAddress((void**)&xBhi, g_xBhi);
    cudaGetSymbolAddress((void**)&xBlo, g_xBlo);
    cudaGetSymbolAddress((void**)&Yhi,  g_Yhi);
    cudaGetSymbolAddress((void**)&Ylo,  g_Ylo);
    cudaGetSymbolAddress((void**)&wTh,  g_wTh);

    __half *w1fh = wTh,            *w1bh = wTh + 65536;
    __half *w2fh = wTh + 2*65536,  *w2bh = wTh + 3*65536;

    const size_t sm1 = (size_t)(2*16*XS1*4 + 2*16*HS1*2 + 16*68*4);
    const size_t sm2 = (size_t)(2*16*XS2*4 + 2*16*HS2*2);

    static bool attr_done = false;
    if (!attr_done) {
        cudaFuncSetAttribute(gemm_fp16_kernel, cudaFuncAttributeMaxDynamicSharedMemorySize, 2*GSTAGE);
        cudaFuncSetAttribute(lstm1_mma_kernel, cudaFuncAttributeMaxDynamicSharedMemorySize, (int)sm1);
        cudaFuncSetAttribute(lstm2_mma_kernel, cudaFuncAttributeMaxDynamicSharedMemorySize, (int)sm2);
        attr_done = true;
    }

    // Launch order arranged so ncu (-s 5 -c 1) profiles lstm1_mma_kernel (#5).
    split_fp16_kernel<<<(BT*128/4 + 255)/256, 256>>>(inputB, xBhi, xBlo, BT*128/4);   // 0
    transpose_fp16_kernel<<<(65536+255)/256, 256>>>(k1f, w1fh, 128, 512);             // 1
    transpose_fp16_kernel<<<(65536+255)/256, 256>>>(k1b, w1bh, 128, 512);             // 2

    const size_t gsm = 2*GSTAGE;
    gemm_fp16_kernel<<<dim3(1024,4), 256, gsm>>>(xBhi, xBlo, w1fh, bb1f, xg1f, BT, 512, 128); // 3
    gemm_fp16_kernel<<<dim3(1024,4), 256, gsm>>>(xBhi, xBlo, w1bh, bb1b, xg1b, BT, 512, 128); // 4

    lstm1_mma_kernel<<<dim3(32,2), 256, sm1>>>(xg1f, xg1b, r1f, r1b, Yhi, Ylo);       // 5 <- profiled

    transpose_fp16_kernel<<<(65536+255)/256, 256>>>(k2f, w2fh, 256, 256);             // 6
    transpose_fp16_kernel<<<(65536+255)/256, 256>>>(k2b, w2bh, 256, 256);             // 7

    gemm_fp16_kernel<<<dim3(1024,2), 256, gsm>>>(Yhi, Ylo, w2fh, bb2f, xg2f, BT, 256, 256);   // 8
    gemm_fp16_kernel<<<dim3(1024,2), 256, gsm>>>(Yhi, Ylo, w2bh, bb2b, xg2b, BT, 256, 256);   // 9

    lstm2_mma_kernel<<<dim3(16,2), 256, sm2>>>(xg2f, xg2b, r2f, r2b, h2);             // 10

    emb_mlp_kernel<<<256, 256>>>(inputA, emb, w1,b1, w2,b2, w3,b3, x64);              // 11
    head_kernel<<<1, 256>>>(x64, h2, wz1,bz1, wz2,bz2, wt1,bt1, wt2,bt2, out);        // 12
}

// round 11
// speedup vs baseline: 1.9191x; 1.1676x over previous
#include <cuda_runtime.h>
#include <cuda_fp16.h>
#include <cooperative_groups.h>
#include <cstdint>
namespace cg = cooperative_groups;

// ------------------------- scratch (device globals) -------------------------
#define BT (256*512)
__device__ float g_x64 [256*64];
__device__ float g_xg1f[(size_t)BT*512];
__device__ float g_xg1b[(size_t)BT*512];
__device__ float g_xg2f[(size_t)BT*256];
__device__ float g_xg2b[(size_t)BT*256];
__device__ float g_h2  [256*128];
__device__ __half g_xBhi[(size_t)BT*128];
__device__ __half g_xBlo[(size_t)BT*128];
__device__ __half g_Yhi [(size_t)BT*256];
__device__ __half g_Ylo [(size_t)BT*256];
__device__ __half g_wTh [4*65536];          // transposed weights [N,K], fp16

// ------------------------- small PTX helpers --------------------------------
__device__ __forceinline__ uint32_t smem_u32(const void* p) {
    uint32_t a;
    asm("{ .reg .u64 t; cvta.to.shared.u64 t, %1; cvt.u32.u64 %0, t; }" : "=r"(a) : "l"(p));
    return a;
}
__device__ __forceinline__ void mma_fp16(float* c, const uint32_t* a, const uint32_t* b) {
    asm volatile("mma.sync.aligned.m16n8k16.row.col.f32.f16.f16.f32 "
        "{%0,%1,%2,%3},{%4,%5,%6,%7},{%8,%9},{%0,%1,%2,%3};"
        : "+f"(c[0]), "+f"(c[1]), "+f"(c[2]), "+f"(c[3])
        : "r"(a[0]), "r"(a[1]), "r"(a[2]), "r"(a[3]), "r"(b[0]), "r"(b[1]));
}
#define LDMATRIX_X4(r0, r1, r2, r3, addr) \
    asm volatile("ldmatrix.sync.aligned.m8n8.x4.shared.b16 {%0,%1,%2,%3}, [%4];" \
        : "=r"(r0), "=r"(r1), "=r"(r2), "=r"(r3) : "r"(addr))
#define CP_ASYNC16(dst, src) asm volatile("cp.async.cg.shared.global [%0], [%1], 16;" :: "r"(dst), "l"(src))
#define CP_COMMIT()          asm volatile("cp.async.commit_group;" ::: "memory")
#define CP_WAIT(n)           asm volatile("cp.async.wait_group %0;" :: "n"(n) : "memory")

#define MBAR_INIT(mb, c) \
    asm volatile("mbarrier.init.shared.b64 [%0], %1;" :: "r"(mb), "r"(c) : "memory")
#define MBAR_ARRIVE_LOCAL(mb) \
    asm volatile("mbarrier.arrive.shared.b64 _, [%0];" :: "r"(mb) : "memory")
#define MBAR_ARRIVE_PEER(mb, peer) \
    asm volatile("{ .reg .b32 ra; mapa.shared::cluster.u32 ra, %0, %1;\n\t" \
                 "mbarrier.arrive.release.cluster.shared::cluster.b64 _, [ra]; }" \
                 :: "r"(mb), "r"(peer) : "memory")
#define MBAR_WAIT_CL(mb, ph) do { \
    uint32_t _m = (mb), _p = (ph), _d; \
    asm volatile("{ .reg .pred p; mbarrier.try_wait.parity.acquire.cluster.shared::cta.b64 p, [%1], %2, 0x989680; selp.b32 %0, 1, 0, p; }" \
        : "=r"(_d) : "r"(_m), "r"(_p) : "memory"); \
    if (!_d) { \
        asm volatile("{ .reg .pred P1;\n\tWL_%=: mbarrier.try_wait.parity.acquire.cluster.shared::cta.b64 P1, [%0], %1, 0x989680;\n\t@P1 bra.uni WD_%=;\n\tbra.uni WL_%=;\n\tWD_%=: }" \
            :: "r"(_m), "r"(_p) : "memory"); \
    } } while (0)

// fast sigmoid: 1/(1+2^(-x*log2e)) via ex2.approx + rcp.approx (~1e-6 rel err)
__device__ __forceinline__ float sigf(float x) {
    float r;
    asm("{ .reg .f32 t;\n\t"
        "mul.f32 t, %1, 0fBFB8AA3B;\n\t"
        "ex2.approx.f32 t, t;\n\t"
        "add.f32 t, t, 0f3F800000;\n\t"
        "rcp.approx.f32 %0, t; }"
        : "=f"(r) : "f"(x));
    return r;
}
__device__ __forceinline__ uint32_t pack_h2(__half a, __half b) {
    __half2 t = __halves2half2(a, b);
    return *(uint32_t*)&t;
}
__device__ __forceinline__ void split_h(float f, __half& hi, __half& lo) {
    hi = __float2half(f);
    lo = __float2half(f - __half2float(hi));
}

// --------- mega-prep: split inputB to fp16 hi/lo + transpose all weights ----
#define SPLIT_N4 (BT*128/4)
__global__ void __launch_bounds__(256)
prep_kernel(const float* __restrict__ inB, __half* __restrict__ hi, __half* __restrict__ lo,
            const float* __restrict__ k1f, const float* __restrict__ k1b,
            const float* __restrict__ k2f, const float* __restrict__ k2b,
            __half* __restrict__ wout)
{
    int idx = blockIdx.x * 256 + threadIdx.x;
    if (idx < SPLIT_N4) {
        float4 v = ((const float4*)inB)[idx];
        __half h0,h1,h2,h3,l0,l1,l2,l3;
        split_h(v.x,h0,l0); split_h(v.y,h1,l1);
        split_h(v.z,h2,l2); split_h(v.w,h3,l3);
        ((uint2*)hi)[idx] = make_uint2(pack_h2(h0,h1), pack_h2(h2,h3));
        ((uint2*)lo)[idx] = make_uint2(pack_h2(l0,l1), pack_h2(l2,l3));
    } else {
        int r = idx - SPLIT_N4;
        if (r < 4*65536) {
            int m = r >> 16, e = r & 65535;
            const float* src = (m == 0) ? k1f : (m == 1) ? k1b : (m == 2) ? k2f : k2b;
            int K = (m < 2) ? 128 : 256, N = (m < 2) ? 512 : 256;
            int n = e / K, k = e - n * K;
            wout[r] = __float2half(src[k * N + n]);
        }
    }
}

// ---- fp16 asymmetric 2-product GEMM + bias (unchanged from R9) -------------
#define GSTAGE 30720
__global__ void __launch_bounds__(256, 2)
gemm_fp16_kernel(const __half* __restrict__ Ahi, const __half* __restrict__ Alo,
                 const __half* __restrict__ W,
                 const float* __restrict__ bias, float* __restrict__ C,
                 int M, int N, int K)
{
    extern __shared__ char smem[];
    const uint32_t smem_base = smem_u32(smem);
    const int tid = threadIdx.x;
    const int lane = tid & 31, wid = tid >> 5;
    const int m0 = blockIdx.x * 128, n0 = blockIdx.y * 128;
    const int wm = (wid >> 2) * 64, wn = (wid & 3) * 32;

    float acc[4][4][4];
    #pragma unroll
    for (int mt = 0; mt < 4; ++mt)
        #pragma unroll
        for (int nt = 0; nt < 4; ++nt)
            #pragma unroll
            for (int q = 0; q < 4; ++q) acc[mt][nt][q] = 0.f;

    const uint32_t lrow = (uint32_t)(lane & 15);
    const uint32_t lcol = (uint32_t)((lane >> 4) * 16);
    uint32_t offA[4], offB[2];
    #pragma unroll
    for (int mt = 0; mt < 4; ++mt)
        offA[mt] = (uint32_t)(wm + mt * 16 + lrow) * 80u + lcol;
    #pragma unroll
    for (int p = 0; p < 2; ++p)
        offB[p] = (uint32_t)(wn + p * 16 + lrow) * 80u + lcol;

    const int nch = K >> 5;
    auto issue = [&](int ch, int stage) {
        const int kc = ch << 5;
        const uint32_t st = smem_base + (uint32_t)stage * GSTAGE;
        #pragma unroll
        for (int i = 0; i < 2; ++i) {
            int idx = tid + i * 256;
            int row = idx >> 2, c = idx & 3;
            uint32_t soff = (uint32_t)(row * 80 + c * 16);
            size_t ga = (size_t)(m0 + row) * K + kc + c * 8;
            size_t gb = (size_t)(n0 + row) * K + kc + c * 8;
            CP_ASYNC16(st + soff,           Ahi + ga);
            CP_ASYNC16(st + 10240u + soff,  Alo + ga);
            CP_ASYNC16(st + 20480u + soff,  W   + gb);
        }
        CP_COMMIT();
    };

    issue(0, 0);
    for (int ch = 0; ch < nch; ++ch) {
        if (ch + 1 < nch) { issue(ch + 1, (ch + 1) & 1); CP_WAIT(1); }
        else             { CP_WAIT(0); }
        __syncthreads();

        const uint32_t stg = smem_base + (uint32_t)(ch & 1) * GSTAGE;
        #pragma unroll
        for (int kk = 0; kk < 2; ++kk) {
            const uint32_t kb = (uint32_t)(kk * 32);
            uint32_t bfr[4][2];
            #pragma unroll
            for (int p = 0; p < 2; ++p) {
                uint32_t r0, r1, r2, r3;
                LDMATRIX_X4(r0, r1, r2, r3, stg + 20480u + offB[p] + kb);
                bfr[2*p][0] = r0; bfr[2*p+1][0] = r1;
                bfr[2*p][1] = r2; bfr[2*p+1][1] = r3;
            }
            #pragma unroll
            for (int mt = 0; mt < 4; ++mt) {
                uint32_t ahi[4], alo[4];
                LDMATRIX_X4(ahi[0], ahi[1], ahi[2], ahi[3], stg + offA[mt] + kb);
                LDMATRIX_X4(alo[0], alo[1], alo[2], alo[3], stg + 10240u + offA[mt] + kb);
                #pragma unroll
                for (int nt = 0; nt < 4; ++nt) {
                    mma_fp16(acc[mt][nt], ahi, bfr[nt]);
                    mma_fp16(acc[mt][nt], alo, bfr[nt]);
                }
            }
        }
        __syncthreads();
    }

    #pragma unroll
    for (int mt = 0; mt < 4; ++mt) {
        int r = m0 + wm + mt * 16 + (lane >> 2);
        #pragma unroll
        for (int nt = 0; nt < 4; ++nt) {
            int col = n0 + wn + nt * 8 + (lane & 3) * 2;
            float b0 = __ldg(bias + col), b1 = __ldg(bias + col + 1);
            float2 v0 = make_float2(acc[mt][nt][0] + b0, acc[mt][nt][1] + b1);
            float2 v1 = make_float2(acc[mt][nt][2] + b0, acc[mt][nt][3] + b1);
            *(float2*)(C + (size_t)r * N + col)       = v0;
            *(float2*)(C + (size_t)(r + 8) * N + col) = v1;
        }
    }
}

// ------------------------- embedding MLP branch -----------------------------
__global__ void __launch_bounds__(256)
emb_mlp_kernel(const int* __restrict__ inputA, const float* __restrict__ emb,
               const float* __restrict__ w1, const float* __restrict__ b1,
               const float* __restrict__ w2, const float* __restrict__ b2,
               const float* __restrict__ w3, const float* __restrict__ b3,
               float* __restrict__ xout)
{
    __shared__ float x0[600], x1[256], x2[128];
    const int b = blockIdx.x, tid = threadIdx.x;
    for (int i = tid; i < 600; i += 256) {
        int la = i / 3, comp = i - la * 3;
        x0[i] = emb[inputA[b*200 + la]*3 + comp];
    }
    __syncthreads();
    {
        float acc = b1[tid];
        #pragma unroll 4
        for (int k = 0; k < 600; ++k) acc += x0[k] * w1[k*256 + tid];
        x1[tid] = fmaxf(acc, 0.f);
    }
    __syncthreads();
    if (tid < 128) {
        float acc = b2[tid];
        #pragma unroll 4
        for (int k = 0; k < 256; ++k) acc += x1[k] * w2[k*128 + tid];
        x2[tid] = fmaxf(acc, 0.f);
    }
    __syncthreads();
    if (tid < 64) {
        float acc = b3[tid];
        #pragma unroll 4
        for (int k = 0; k < 128; ++k) acc += x2[k] * w3[k*64 + tid];
        xout[b*64 + tid] = fmaxf(acc, 0.f);
    }
}

// ------------- LSTM layer 1 (H=128) — fp16-k16 recurrence v2 ----------------
// R9 + (a) mbarrier cluster handshake instead of cluster.sync (~-350 cyc/step),
// (b) 3-stage xg cp.async pipeline, (c) fast sigmoid.
#define XS1 516
#define HS1 136
__global__ void __cluster_dims__(2,1,1) __launch_bounds__(256, 1)
lstm1_mma_kernel(const float* __restrict__ xg1f, const float* __restrict__ xg1b,
                 const float* __restrict__ r1f,  const float* __restrict__ r1b,
                 __half* __restrict__ Yhi, __half* __restrict__ Ylo)
{
    extern __shared__ char smraw[];
    float*  sxg   = (float*)smraw;                               // 3*16*XS1 f32
    __half* hbufh = (__half*)(smraw + 3*16*XS1*4);               // 2*16*HS1 f16
    float*  ybuf  = (float*)(smraw + 3*16*XS1*4 + 2*16*HS1*2);   // 16*68 f32
    const uint32_t mbar = smem_u32(smraw + 3*16*XS1*4 + 2*16*HS1*2 + 16*68*4);

    cg::cluster_group cl = cg::this_cluster();
    const int rank = cl.block_rank();
    const int dir  = blockIdx.y;
    const int b0   = (blockIdx.x >> 1) * 16;
    const int tid  = threadIdx.x;
    const int lane = tid & 31, w = tid >> 5;
    const int q    = lane & 3;
    const float* xg = dir ? xg1b : xg1f;
    const float* Wr = dir ? r1b : r1f;

    uint32_t bfr[4][8][2];
    #pragma unroll
    for (int nt = 0; nt < 4; ++nt) {
        int n_local = w * 32 + nt * 8 + (lane >> 2);
        int G = (n_local & 3) * 128 + rank * 64 + (n_local >> 2);
        #pragma unroll
        for (int kt = 0; kt < 8; ++kt)
            #pragma unroll
            for (int p = 0; p < 2; ++p) {
                int k = kt * 16 + q * 2 + p * 8;
                bfr[nt][kt][p] = pack_h2(__float2half(Wr[k * 512 + G]),
                                         __float2half(Wr[(k + 1) * 512 + G]));
            }
    }

    for (int i = tid; i < 2 * 16 * HS1; i += 256) hbufh[i] = __float2half(0.f);
    if (tid == 0) MBAR_INIT(mbar, 2);

    const uint32_t hb32 = smem_u32(hbufh);
    const uint32_t xbase = smem_u32(sxg);
    const uint32_t lmbase = (uint32_t)(((lane & 15) * HS1 + ((lane >> 4) << 3)) * 2);
    const bool isState = (lane & 1);
    const int g0 = (q & 1) * 2;
    int colA[4], hj[4], al[4];
    #pragma unroll
    for (int nt = 0; nt < 4; ++nt) {
        int a_local = w * 8 + nt * 2 + (q >> 1);
        colA[nt] = g0 * 128 + rank * 64 + a_local;
        hj[nt]   = rank * 64 + a_local;
        al[nt]   = a_local;
    }
    const int r = lane >> 2;

    float cst[4][2];
    #pragma unroll
    for (int nt = 0; nt < 4; ++nt) { cst[nt][0] = 0.f; cst[nt][1] = 0.f; }

    auto issue_xg = [&](int tt, int stage) {
        const uint32_t dst0 = xbase + (uint32_t)(stage * 16 * XS1 * 4);
        #pragma unroll
        for (int i = 0; i < 8; ++i) {
            int idx = tid + i * 256;
            int row = idx >> 7, c4 = idx & 127;
            CP_ASYNC16(dst0 + (uint32_t)((row * XS1 + c4 * 4) * 4),
                       xg + ((size_t)(b0 + row) * 512 + tt) * 512 + c4 * 4);
        }
        CP_COMMIT();
    };

    __half* peer_h = (__half*)cl.map_shared_rank((void*)hbufh, rank ^ 1);
    __syncthreads();
    cl.sync();   // mbarrier init + hbuf zero visible cluster-wide

    issue_xg(dir ? 511 : 0, 0);
    issue_xg(dir ? 510 : 1, 1);

    for (int t = 0; t < 512; ++t) {
        const int tt  = dir ? (511 - t) : t;
        const int cur = t & 1, nxt = cur ^ 1;

        if (t + 2 < 512)      { issue_xg(dir ? (509 - t) : (t + 2), (t + 2) % 3); CP_WAIT(2); }
        else if (t + 1 < 512) { CP_WAIT(1); }
        else                  { CP_WAIT(0); }
        __syncthreads();

        const float* xs = sxg + (t % 3) * 16 * XS1;
        float acc[4][4];
        #pragma unroll
        for (int nt = 0; nt < 4; ++nt) {
            acc[nt][0] = xs[r * XS1 + colA[nt]];
            acc[nt][1] = xs[r * XS1 + colA[nt] + 128];
            acc[nt][2] = xs[(r + 8) * XS1 + colA[nt]];
            acc[nt][3] = xs[(r + 8) * XS1 + colA[nt] + 128];
        }

        const uint32_t abase = hb32 + (uint32_t)(cur * 16 * HS1 * 2) + lmbase;
        #pragma unroll
        for (int kt = 0; kt < 8; ++kt) {
            uint32_t a0, a1, a2, a3;
            LDMATRIX_X4(a0, a1, a2, a3, abase + (uint32_t)(kt * 32));
            uint32_t afr[4] = {a0, a1, a2, a3};
            #pragma unroll
            for (int nt = 0; nt < 4; ++nt)
                mma_fp16(acc[nt], afr, bfr[nt][kt]);
        }

        #pragma unroll
        for (int nt = 0; nt < 4; ++nt) {
            float v0 = isState ? fmaxf(acc[nt][0], 0.f) : sigf(acc[nt][0]);
            float v1 = sigf(acc[nt][1]);
            float v2 = isState ? fmaxf(acc[nt][2], 0.f) : sigf(acc[nt][2]);
            float v3 = sigf(acc[nt][3]);
            float s0 = __shfl_xor_sync(0xffffffffu, v0, 1);
            float s1 = __shfl_xor_sync(0xffffffffu, v1, 1);
            float s2 = __shfl_xor_sync(0xffffffffu, v2, 1);
            float s3 = __shfl_xor_sync(0xffffffffu, v3, 1);
            if (isState) {
                float c0 = s1 * cst[nt][0] + s0 * v0;
                float c1 = s3 * cst[nt][1] + s2 * v2;
                cst[nt][0] = c0; cst[nt][1] = c1;
                float h0 = v1 * fmaxf(c0, 0.f);
                float h1 = v3 * fmaxf(c1, 0.f);
                __half h0h = __float2half(h0);
                __half h1h = __float2half(h1);
                int o0 = nxt * 16 * HS1 + r * HS1 + hj[nt];
                int o1 = nxt * 16 * HS1 + (r + 8) * HS1 + hj[nt];
                hbufh[o0] = h0h;  hbufh[o1] = h1h;
                peer_h[o0] = h0h; peer_h[o1] = h1h;
                ybuf[r * 68 + al[nt]]       = h0;
                ybuf[(r + 8) * 68 + al[nt]] = h1;
            }
        }

        // cluster handshake (replaces cluster.sync): release peer stores,
        // acquire peer's. One barrier, count=2, phase parity = t&1.
        __syncthreads();
        if (tid == 0) {
            MBAR_ARRIVE_LOCAL(mbar);
            MBAR_ARRIVE_PEER(mbar, rank ^ 1);
        }
        MBAR_WAIT_CL(mbar, t & 1);

        // coalesced Y store: own 64-col slice, split to fp16 hi/lo
        {
            int row = tid >> 4, c4 = tid & 15;
            float4 v = *(const float4*)&ybuf[row * 68 + c4 * 4];
            size_t idx = ((size_t)(b0 + row) * 512 + tt) * 256
                         + dir * 128 + rank * 64 + c4 * 4;
            __half h0,h1,h2,h3,l0,l1,l2,l3;
            split_h(v.x,h0,l0); split_h(v.y,h1,l1);
            split_h(v.z,h2,l2); split_h(v.w,h3,l3);
            *(uint2*)&Yhi[idx] = make_uint2(pack_h2(h0,h1), pack_h2(h2,h3));
            *(uint2*)&Ylo[idx] = make_uint2(pack_h2(l0,l1), pack_h2(l2,l3));
        }
    }
}

// ------------- LSTM layer 2 (H=64) — fp16-k16 recurrence v2 -----------------
#define XS2 260
#define HS2 72
__global__ void __launch_bounds__(256, 1)
lstm2_mma_kernel(const float* __restrict__ xg2f, const float* __restrict__ xg2b,
                 const float* __restrict__ r2f,  const float* __restrict__ r2b,
                 float* __restrict__ hout)
{
    extern __shared__ char smraw[];
    float*  sxg   = (float*)smraw;                     // 3*16*XS2 f32
    __half* hbufh = (__half*)(smraw + 3*16*XS2*4);     // 2*16*HS2 f16

    const int dir = blockIdx.y;
    const int b0  = blockIdx.x * 16;
    const int tid = threadIdx.x;
    const int lane = tid & 31, w = tid >> 5;
    const int q = lane & 3;
    const float* xg = dir ? xg2b : xg2f;
    const float* Wr = dir ? r2b : r2f;

    uint32_t bfr[4][4][2];
    #pragma unroll
    for (int nt = 0; nt < 4; ++nt) {
        int n_local = w * 32 + nt * 8 + (lane >> 2);
        int G = (n_local & 3) * 64 + (n_local >> 2);
        #pragma unroll
        for (int kt = 0; kt < 4; ++kt)
            #pragma unroll
            for (int p = 0; p < 2; ++p) {
                int k = kt * 16 + q * 2 + p * 8;
                bfr[nt][kt][p] = pack_h2(__float2half(Wr[k * 256 + G]),
                                         __float2half(Wr[(k + 1) * 256 + G]));
            }
    }

    for (int i = tid; i < 2 * 16 * HS2; i += 256) hbufh[i] = __float2half(0.f);

    const uint32_t hb32 = smem_u32(hbufh);
    const uint32_t xbase = smem_u32(sxg);
    const uint32_t lmbase = (uint32_t)(((lane & 15) * HS2 + ((lane >> 4) << 3)) * 2);
    const bool isState = (lane & 1);
    const int g0 = (q & 1) * 2;
    int colA[4], hj[4];
    #pragma unroll
    for (int nt = 0; nt < 4; ++nt) {
        int a_local = w * 8 + nt * 2 + (q >> 1);
        colA[nt] = g0 * 64 + a_local;
        hj[nt]   = a_local;
    }
    const int r = lane >> 2;

    float cst[4][2];
    #pragma unroll
    for (int nt = 0; nt < 4; ++nt) { cst[nt][0] = 0.f; cst[nt][1] = 0.f; }

    auto issue_xg = [&](int tt, int stage) {
        const uint32_t dst0 = xbase + (uint32_t)(stage * 16 * XS2 * 4);
        #pragma unroll
        for (int i = 0; i < 4; ++i) {
            int idx = tid + i * 256;
            int row = idx >> 6, c4 = idx & 63;
            CP_ASYNC16(dst0 + (uint32_t)((row * XS2 + c4 * 4) * 4),
                       xg + ((size_t)(b0 + row) * 512 + tt) * 256 + c4 * 4);
        }
        CP_COMMIT();
    };

    __syncthreads();
    issue_xg(dir ? 511 : 0, 0);
    issue_xg(dir ? 510 : 1, 1);

    for (int t = 0; t < 512; ++t) {
        const int tt  = dir ? (511 - t) : t;
        const int cur = t & 1, nxt = cur ^ 1;

        if (t + 2 < 512)      { issue_xg(dir ? (509 - t) : (t + 2), (t + 2) % 3); CP_WAIT(2); }
        else if (t + 1 < 512) { CP_WAIT(1); }
        else                  { CP_WAIT(0); }
        __syncthreads();

        const float* xs = sxg + (t % 3) * 16 * XS2;
        float acc[4][4];
        #pragma unroll
        for (int nt = 0; nt < 4; ++nt) {
            acc[nt][0] = xs[r * XS2 + colA[nt]];
            acc[nt][1] = xs[r * XS2 + colA[nt] + 64];
            acc[nt][2] = xs[(r + 8) * XS2 + colA[nt]];
            acc[nt][3] = xs[(r + 8) * XS2 + colA[nt] + 64];
        }

        const uint32_t abase = hb32 + (uint32_t)(cur * 16 * HS2 * 2) + lmbase;
        #pragma unroll
        for (int kt = 0; kt < 4; ++kt) {
            uint32_t a0, a1, a2, a3;
            LDMATRIX_X4(a0, a1, a2, a3, abase + (uint32_t)(kt * 32));
            uint32_t afr[4] = {a0, a1, a2, a3};
            #pragma unroll
            for (int nt = 0; nt < 4; ++nt)
                mma_fp16(acc[nt], afr, bfr[nt][kt]);
        }

        #pragma unroll
        for (int nt = 0; nt < 4; ++nt) {
            float v0 = isState ? fmaxf(acc[nt][0], 0.f) : sigf(acc[nt][0]);
            float v1 = sigf(acc[nt][1]);
            float v2 = isState ? fmaxf(acc[nt][2], 0.f) : sigf(acc[nt][2]);
            float v3 = sigf(acc[nt][3]);
            float s0 = __shfl_xor_sync(0xffffffffu, v0, 1);
            float s1 = __shfl_xor_sync(0xffffffffu, v1, 1);
            float s2 = __shfl_xor_sync(0xffffffffu, v2, 1);
            float s3 = __shfl_xor_sync(0xffffffffu, v3, 1);
            if (isState) {
                float c0 = s1 * cst[nt][0] + s0 * v0;
                float c1 = s3 * cst[nt][1] + s2 * v2;
                cst[nt][0] = c0; cst[nt][1] = c1;
                float h0 = v1 * fmaxf(c0, 0.f);
                float h1 = v3 * fmaxf(c1, 0.f);
                hbufh[nxt * 16 * HS2 + r * HS2 + hj[nt]]       = __float2half(h0);
                hbufh[nxt * 16 * HS2 + (r + 8) * HS2 + hj[nt]] = __float2half(h1);
                if (t == 511) {
                    hout[(size_t)(b0 + r) * 128 + dir * 64 + hj[nt]]     = h0;
                    hout[(size_t)(b0 + r + 8) * 128 + dir * 64 + hj[nt]] = h1;
                }
            }
        }
        __syncthreads();
    }
}

// ------------------------------ heads ---------------------------------------
__global__ void __launch_bounds__(256)
head_kernel(const float* __restrict__ x64, const float* __restrict__ h2,
            const float* __restrict__ wz1, const float* __restrict__ bz1,
            const float* __restrict__ wz2, const float* __restrict__ bz2,
            const float* __restrict__ wt1, const float* __restrict__ bt1,
            const float* __restrict__ wt2, const float* __restrict__ bt2,
            float* __restrict__ out)
{
    const int b = threadIdx.x;
    float comb[192];
    #pragma unroll 4
    for (int k = 0; k < 64; ++k)  comb[k]      = x64[b*64 + k];
    #pragma unroll 4
    for (int k = 0; k < 128; ++k) comb[64 + k] = h2[b*128 + k];

    float z0 = bz1[0], z1 = bz1[1], t0 = bt1[0], t1 = bt1[1];
    #pragma unroll 4
    for (int k = 0; k < 192; ++k) {
        float v = comb[k];
        z0 += v * wz1[k*2 + 0]; z1 += v * wz1[k*2 + 1];
        t0 += v * wt1[k*2 + 0]; t1 += v * wt1[k*2 + 1];
    }
    out[b]       = fmaxf(z0,0.f)*wz2[0] + fmaxf(z1,0.f)*wz2[1] + bz2[0];
    out[256 + b] = fmaxf(t0,0.f)*wt2[0] + fmaxf(t1,0.f)*wt2[1] + bt2[0];
}

// ------------------------------ launcher ------------------------------------
extern "C" void kernel_launch(void* const* d_in, const int* in_sizes, int n_in,
                              void* d_out, int out_size)
{
    const int*   inputA = (const int*)  d_in[0];
    const float* inputB = (const float*)d_in[1];
    const float* emb = (const float*)d_in[2];
    const float *w1=(const float*)d_in[3],  *b1=(const float*)d_in[4];
    const float *w2=(const float*)d_in[5],  *b2=(const float*)d_in[6];
    const float *w3=(const float*)d_in[7],  *b3=(const float*)d_in[8];
    const float *k1f=(const float*)d_in[9],  *r1f=(const float*)d_in[10], *bb1f=(const float*)d_in[11];
    const float *k1b=(const float*)d_in[12], *r1b=(const float*)d_in[13], *bb1b=(const float*)d_in[14];
    const float *k2f=(const float*)d_in[15], *r2f=(const float*)d_in[16], *bb2f=(const float*)d_in[17];
    const float *k2b=(const float*)d_in[18], *r2b=(const float*)d_in[19], *bb2b=(const float*)d_in[20];
    const float *wz1=(const float*)d_in[21], *bz1=(const float*)d_in[22];
    const float *wz2=(const float*)d_in[23], *bz2=(const float*)d_in[24];
    const float *wt1=(const float*)d_in[25], *bt1=(const float*)d_in[26];
    const float *wt2=(const float*)d_in[27], *bt2=(const float*)d_in[28];
    float* out = (float*)d_out;

    float *xg1f, *xg1b, *xg2f, *xg2b, *x64, *h2;
    __half *xBhi, *xBlo, *Yhi, *Ylo, *wTh;
    cudaGetSymbolAddress((void**)&xg1f, g_xg1f);
    cudaGetSymbolAddress((void**)&xg1b, g_xg1b);
    cudaGetSymbolAddress((void**)&xg2f, g_xg2f);
    cudaGetSymbolAddress((void**)&xg2b, g_xg2b);
    cudaGetSymbolAddress((void**)&x64,  g_x64);
    cudaGetSymbolAddress((void**)&h2,   g_h2);
    cudaGetSymbolAddress((void**)&xBhi, g_xBhi);
    cudaGetSymbolAddress((void**)&xBlo, g_xBlo);
    cudaGetSymbolAddress((void**)&Yhi,  g_Yhi);
    cudaGetSymbolAddress((void**)&Ylo,  g_Ylo);
    cudaGetSymbolAddress((void**)&wTh,  g_wTh);

    __half *w1fh = wTh,            *w1bh = wTh + 65536;
    __half *w2fh = wTh + 2*65536,  *w2bh = wTh + 3*65536;

    const size_t sm1 = (size_t)(3*16*XS1*4 + 2*16*HS1*2 + 16*68*4 + 16);
    const size_t sm2 = (size_t)(3*16*XS2*4 + 2*16*HS2*2);

    static bool attr_done = false;
    if (!attr_done) {
        cudaFuncSetAttribute(gemm_fp16_kernel, cudaFuncAttributeMaxDynamicSharedMemorySize, 2*GSTAGE);
        cudaFuncSetAttribute(lstm1_mma_kernel, cudaFuncAttributeMaxDynamicSharedMemorySize, (int)sm1);
        cudaFuncSetAttribute(lstm2_mma_kernel, cudaFuncAttributeMaxDynamicSharedMemorySize, (int)sm2);
        attr_done = true;
    }

    // Launch order: lstm1 at index 3 (ncu -s 5 with observed +2 offset -> lstm1).
    prep_kernel<<<(SPLIT_N4 + 4*65536 + 255)/256, 256>>>(inputB, xBhi, xBlo,
                                                         k1f, k1b, k2f, k2b, wTh);  // 0
    const size_t gsm = 2*GSTAGE;
    gemm_fp16_kernel<<<dim3(1024,4), 256, gsm>>>(xBhi, xBlo, w1fh, bb1f, xg1f, BT, 512, 128); // 1
    gemm_fp16_kernel<<<dim3(1024,4), 256, gsm>>>(xBhi, xBlo, w1bh, bb1b, xg1b, BT, 512, 128); // 2

    lstm1_mma_kernel<<<dim3(32,2), 256, sm1>>>(xg1f, xg1b, r1f, r1b, Yhi, Ylo);     // 3

    gemm_fp16_kernel<<<dim3(1024,2), 256, gsm>>>(Yhi, Ylo, w2fh, bb2f, xg2f, BT, 256, 256);   // 4
    gemm_fp16_kernel<<<dim3(1024,2), 256, gsm>>>(Yhi, Ylo, w2bh, bb2b, xg2b, BT, 256, 256);   // 5

    lstm2_mma_kernel<<<dim3(16,2), 256, sm2>>>(xg2f, xg2b, r2f, r2b, h2);           // 6

    emb_mlp_kernel<<<256, 256>>>(inputA, emb, w1,b1, w2,b2, w3,b3, x64);            // 7
    head_kernel<<<1, 256>>>(x64, h2, wz1,bz1, wz2,bz2, wt1,bt1, wt2,bt2, out);      // 8
}

// round 13
// speedup vs baseline: 2.4442x; 1.2736x over previous
#include <cuda_runtime.h>
#include <cuda_fp16.h>
#include <cooperative_groups.h>
#include <cstdint>
namespace cg = cooperative_groups;

// ------------------------- scratch (device globals) -------------------------
#define BT (256*512)
__device__ float g_x64 [256*64];
__device__ float g_xg1f[(size_t)BT*512];
__device__ float g_xg1b[(size_t)BT*512];
__device__ float g_xg2f[(size_t)BT*256];
__device__ float g_xg2b[(size_t)BT*256];
__device__ float g_h2  [256*128];
__device__ __half g_xBhi[(size_t)BT*128];
__device__ __half g_xBlo[(size_t)BT*128];
__device__ __half g_Yhi [(size_t)BT*256];
__device__ __half g_Ylo [(size_t)BT*256];
__device__ __half g_wTh [4*65536];          // transposed weights [N,K], fp16

// ------------------------- small PTX helpers --------------------------------
__device__ __forceinline__ uint32_t smem_u32(const void* p) {
    uint32_t a;
    asm("{ .reg .u64 t; cvta.to.shared.u64 t, %1; cvt.u32.u64 %0, t; }" : "=r"(a) : "l"(p));
    return a;
}
__device__ __forceinline__ void mma_fp16(float* c, const uint32_t* a, const uint32_t* b) {
    asm volatile("mma.sync.aligned.m16n8k16.row.col.f32.f16.f16.f32 "
        "{%0,%1,%2,%3},{%4,%5,%6,%7},{%8,%9},{%0,%1,%2,%3};"
        : "+f"(c[0]), "+f"(c[1]), "+f"(c[2]), "+f"(c[3])
        : "r"(a[0]), "r"(a[1]), "r"(a[2]), "r"(a[3]), "r"(b[0]), "r"(b[1]));
}
#define LDMATRIX_X4(r0, r1, r2, r3, addr) \
    asm volatile("ldmatrix.sync.aligned.m8n8.x4.shared.b16 {%0,%1,%2,%3}, [%4];" \
        : "=r"(r0), "=r"(r1), "=r"(r2), "=r"(r3) : "r"(addr))
#define CP_ASYNC16(dst, src) asm volatile("cp.async.cg.shared.global [%0], [%1], 16;" :: "r"(dst), "l"(src))
#define CP_COMMIT()          asm volatile("cp.async.commit_group;" ::: "memory")
#define CP_WAIT(n)           asm volatile("cp.async.wait_group %0;" :: "n"(n) : "memory")

#define MBAR_INIT(mb, c) \
    asm volatile("mbarrier.init.shared.b64 [%0], %1;" :: "r"(mb), "r"(c) : "memory")
#define MBAR_ARRIVE_LOCAL(mb) \
    asm volatile("mbarrier.arrive.shared.b64 _, [%0];" :: "r"(mb) : "memory")
#define MBAR_ARRIVE_PEER(mb, peer) \
    asm volatile("{ .reg .b32 ra; mapa.shared::cluster.u32 ra, %0, %1;\n\t" \
                 "mbarrier.arrive.release.cluster.shared::cluster.b64 _, [ra]; }" \
                 :: "r"(mb), "r"(peer) : "memory")
#define MBAR_WAIT_CL(mb, ph) do { \
    uint32_t _m = (mb), _p = (ph), _d; \
    asm volatile("{ .reg .pred p; mbarrier.try_wait.parity.acquire.cluster.shared::cta.b64 p, [%1], %2, 0x989680; selp.b32 %0, 1, 0, p; }" \
        : "=r"(_d) : "r"(_m), "r"(_p) : "memory"); \
    if (!_d) { \
        asm volatile("{ .reg .pred P1;\n\tWL_%=: mbarrier.try_wait.parity.acquire.cluster.shared::cta.b64 P1, [%0], %1, 0x989680;\n\t@P1 bra.uni WD_%=;\n\tbra.uni WL_%=;\n\tWD_%=: }" \
            :: "r"(_m), "r"(_p) : "memory"); \
    } } while (0)

#define CLUSTER_ARRIVE() asm volatile("barrier.cluster.arrive.aligned;" ::: "memory")
#define CLUSTER_WAIT()   asm volatile("barrier.cluster.wait.aligned;" ::: "memory")

// fast sigmoid: 1/(1+2^(-x*log2e)) via ex2.approx + rcp.approx (~1e-6 rel err)
__device__ __forceinline__ float sigf(float x) {
    float r;
    asm("{ .reg .f32 t;\n\t"
        "mul.f32 t, %1, 0fBFB8AA3B;\n\t"
        "ex2.approx.f32 t, t;\n\t"
        "add.f32 t, t, 0f3F800000;\n\t"
        "rcp.approx.f32 %0, t; }"
        : "=f"(r) : "f"(x));
    return r;
}
__device__ __forceinline__ uint32_t pack_h2(__half a, __half b) {
    __half2 t = __halves2half2(a, b);
    return *(uint32_t*)&t;
}
__device__ __forceinline__ void split_h(float f, __half& hi, __half& lo) {
    hi = __float2half(f);
    lo = __float2half(f - __half2float(hi));
}

// --------- mega-prep: split inputB to fp16 hi/lo + transpose all weights ----
#define SPLIT_N4 (BT*128/4)
__global__ void __launch_bounds__(256)
prep_kernel(const float* __restrict__ inB, __half* __restrict__ hi, __half* __restrict__ lo,
            const float* __restrict__ k1f, const float* __restrict__ k1b,
            const float* __restrict__ k2f, const float* __restrict__ k2b,
            __half* __restrict__ wout)
{
    int idx = blockIdx.x * 256 + threadIdx.x;
    if (idx < SPLIT_N4) {
        float4 v = ((const float4*)inB)[idx];
        __half h0,h1,h2,h3,l0,l1,l2,l3;
        split_h(v.x,h0,l0); split_h(v.y,h1,l1);
        split_h(v.z,h2,l2); split_h(v.w,h3,l3);
        ((uint2*)hi)[idx] = make_uint2(pack_h2(h0,h1), pack_h2(h2,h3));
        ((uint2*)lo)[idx] = make_uint2(pack_h2(l0,l1), pack_h2(l2,l3));
    } else {
        int r = idx - SPLIT_N4;
        if (r < 4*65536) {
            int m = r >> 16, e = r & 65535;
            const float* src = (m == 0) ? k1f : (m == 1) ? k1b : (m == 2) ? k2f : k2b;
            int K = (m < 2) ? 128 : 256, N = (m < 2) ? 512 : 256;
            int n = e / K, k = e - n * K;
            wout[r] = __float2half(src[k * N + n]);
        }
    }
}

// ---- fp16 asymmetric 2-product GEMM + bias (unchanged from R9/R10) ---------
#define GSTAGE 30720
__global__ void __launch_bounds__(256, 2)
gemm_fp16_kernel(const __half* __restrict__ Ahi, const __half* __restrict__ Alo,
                 const __half* __restrict__ W,
                 const float* __restrict__ bias, float* __restrict__ C,
                 int M, int N, int K)
{
    extern __shared__ char smem[];
    const uint32_t smem_base = smem_u32(smem);
    const int tid = threadIdx.x;
    const int lane = tid & 31, wid = tid >> 5;
    const int m0 = blockIdx.x * 128, n0 = blockIdx.y * 128;
    const int wm = (wid >> 2) * 64, wn = (wid & 3) * 32;

    float acc[4][4][4];
    #pragma unroll
    for (int mt = 0; mt < 4; ++mt)
        #pragma unroll
        for (int nt = 0; nt < 4; ++nt)
            #pragma unroll
            for (int q = 0; q < 4; ++q) acc[mt][nt][q] = 0.f;

    const uint32_t lrow = (uint32_t)(lane & 15);
    const uint32_t lcol = (uint32_t)((lane >> 4) * 16);
    uint32_t offA[4], offB[2];
    #pragma unroll
    for (int mt = 0; mt < 4; ++mt)
        offA[mt] = (uint32_t)(wm + mt * 16 + lrow) * 80u + lcol;
    #pragma unroll
    for (int p = 0; p < 2; ++p)
        offB[p] = (uint32_t)(wn + p * 16 + lrow) * 80u + lcol;

    const int nch = K >> 5;
    auto issue = [&](int ch, int stage) {
        const int kc = ch << 5;
        const uint32_t st = smem_base + (uint32_t)stage * GSTAGE;
        #pragma unroll
        for (int i = 0; i < 2; ++i) {
            int idx = tid + i * 256;
            int row = idx >> 2, c = idx & 3;
            uint32_t soff = (uint32_t)(row * 80 + c * 16);
            size_t ga = (size_t)(m0 + row) * K + kc + c * 8;
            size_t gb = (size_t)(n0 + row) * K + kc + c * 8;
            CP_ASYNC16(st + soff,           Ahi + ga);
            CP_ASYNC16(st + 10240u + soff,  Alo + ga);
            CP_ASYNC16(st + 20480u + soff,  W   + gb);
        }
        CP_COMMIT();
    };

    issue(0, 0);
    for (int ch = 0; ch < nch; ++ch) {
        if (ch + 1 < nch) { issue(ch + 1, (ch + 1) & 1); CP_WAIT(1); }
        else             { CP_WAIT(0); }
        __syncthreads();

        const uint32_t stg = smem_base + (uint32_t)(ch & 1) * GSTAGE;
        #pragma unroll
        for (int kk = 0; kk < 2; ++kk) {
            const uint32_t kb = (uint32_t)(kk * 32);
            uint32_t bfr[4][2];
            #pragma unroll
            for (int p = 0; p < 2; ++p) {
                uint32_t r0, r1, r2, r3;
                LDMATRIX_X4(r0, r1, r2, r3, stg + 20480u + offB[p] + kb);
                bfr[2*p][0] = r0; bfr[2*p+1][0] = r1;
                bfr[2*p][1] = r2; bfr[2*p+1][1] = r3;
            }
            #pragma unroll
            for (int mt = 0; mt < 4; ++mt) {
                uint32_t ahi[4], alo[4];
                LDMATRIX_X4(ahi[0], ahi[1], ahi[2], ahi[3], stg + offA[mt] + kb);
                LDMATRIX_X4(alo[0], alo[1], alo[2], alo[3], stg + 10240u + offA[mt] + kb);
                #pragma unroll
                for (int nt = 0; nt < 4; ++nt) {
                    mma_fp16(acc[mt][nt], ahi, bfr[nt]);
                    mma_fp16(acc[mt][nt], alo, bfr[nt]);
                }
            }
        }
        __syncthreads();
    }

    #pragma unroll
    for (int mt = 0; mt < 4; ++mt) {
        int r = m0 + wm + mt * 16 + (lane >> 2);
        #pragma unroll
        for (int nt = 0; nt < 4; ++nt) {
            int col = n0 + wn + nt * 8 + (lane & 3) * 2;
            float b0 = __ldg(bias + col), b1 = __ldg(bias + col + 1);
            float2 v0 = make_float2(acc[mt][nt][0] + b0, acc[mt][nt][1] + b1);
            float2 v1 = make_float2(acc[mt][nt][2] + b0, acc[mt][nt][3] + b1);
            *(float2*)(C + (size_t)r * N + col)       = v0;
            *(float2*)(C + (size_t)(r + 8) * N + col) = v1;
        }
    }
}

// ------------------------- embedding MLP branch -----------------------------
__global__ void __launch_bounds__(256)
emb_mlp_kernel(const int* __restrict__ inputA, const float* __restrict__ emb,
               const float* __restrict__ w1, const float* __restrict__ b1,
               const float* __restrict__ w2, const float* __restrict__ b2,
               const float* __restrict__ w3, const float* __restrict__ b3,
               float* __restrict__ xout)
{
    __shared__ float x0[600], x1[256], x2[128];
    const int b = blockIdx.x, tid = threadIdx.x;
    for (int i = tid; i < 600; i += 256) {
        int la = i / 3, comp = i - la * 3;
        x0[i] = emb[inputA[b*200 + la]*3 + comp];
    }
    __syncthreads();
    {
        float acc = b1[tid];
        #pragma unroll 4
        for (int k = 0; k < 600; ++k) acc += x0[k] * w1[k*256 + tid];
        x1[tid] = fmaxf(acc, 0.f);
    }
    __syncthreads();
    if (tid < 128) {
        float acc = b2[tid];
        #pragma unroll 4
        for (int k = 0; k < 256; ++k) acc += x1[k] * w2[k*128 + tid];
        x2[tid] = fmaxf(acc, 0.f);
    }
    __syncthreads();
    if (tid < 64) {
        float acc = b3[tid];
        #pragma unroll 4
        for (int k = 0; k < 128; ++k) acc += x2[k] * w3[k*64 + tid];
        xout[b*64 + tid] = fmaxf(acc, 0.f);
    }
}

// ------------- LSTM layer 1 (H=128) — fp16 recurrence, 512 threads ----------
// R11 + FIX: trailing cluster barrier so no CTA exits while the peer's final
// step DSMEM (peer_h) writes are still in flight (R11's ULF root cause).
#define XS1 516
#define HS1 136
__global__ void __cluster_dims__(2,1,1) __launch_bounds__(512, 1)
lstm1_mma_kernel(const float* __restrict__ xg1f, const float* __restrict__ xg1b,
                 const float* __restrict__ r1f,  const float* __restrict__ r1b,
                 __half* __restrict__ Yhi, __half* __restrict__ Ylo)
{
    extern __shared__ char smraw[];
    float*  sxg   = (float*)smraw;                               // 3*16*XS1 f32
    __half* hbufh = (__half*)(smraw + 3*16*XS1*4);               // 2*16*HS1 f16
    float*  ybuf  = (float*)(smraw + 3*16*XS1*4 + 2*16*HS1*2);   // 2*16*68 f32
    const uint32_t mbar = smem_u32(smraw + 3*16*XS1*4 + 2*16*HS1*2 + 2*16*68*4);

    cg::cluster_group cl = cg::this_cluster();
    const int rank = cl.block_rank();
    const int dir  = blockIdx.y;
    const int b0   = (blockIdx.x >> 1) * 16;
    const int tid  = threadIdx.x;
    const int lane = tid & 31, w = tid >> 5;          // w in 0..15
    const int q    = lane & 3;
    const float* xg = dir ? xg1b : xg1f;
    const float* Wr = dir ? r1b : r1f;

    // fp16 weight fragments: warp covers 16 gate cols (nt = 0..1)
    uint32_t bfr[2][8][2];
    #pragma unroll
    for (int nt = 0; nt < 2; ++nt) {
        int n_local = w * 16 + nt * 8 + (lane >> 2);
        int G = (n_local & 3) * 128 + rank * 64 + (n_local >> 2);
        #pragma unroll
        for (int kt = 0; kt < 8; ++kt)
            #pragma unroll
            for (int p = 0; p < 2; ++p) {
                int k = kt * 16 + q * 2 + p * 8;
                bfr[nt][kt][p] = pack_h2(__float2half(Wr[k * 512 + G]),
                                         __float2half(Wr[(k + 1) * 512 + G]));
            }
    }

    for (int i = tid; i < 2 * 16 * HS1; i += 512) hbufh[i] = __float2half(0.f);
    if (tid == 0) MBAR_INIT(mbar, 2);

    const uint32_t hb32 = smem_u32(hbufh);
    const uint32_t xbase = smem_u32(sxg);
    const uint32_t lmbase = (uint32_t)(((lane & 15) * HS1 + ((lane >> 4) << 3)) * 2);
    const bool isState = (lane & 1);
    const int g0 = (q & 1) * 2;
    int colA[2], hj[2], al[2];
    #pragma unroll
    for (int nt = 0; nt < 2; ++nt) {
        int a_local = w * 4 + nt * 2 + (q >> 1);
        colA[nt] = g0 * 128 + rank * 64 + a_local;
        hj[nt]   = rank * 64 + a_local;
        al[nt]   = a_local;
    }
    const int r = lane >> 2;

    float cst[2][2];
    #pragma unroll
    for (int nt = 0; nt < 2; ++nt) { cst[nt][0] = 0.f; cst[nt][1] = 0.f; }

    auto issue_xg = [&](int tt, int stage) {
        const uint32_t dst0 = xbase + (uint32_t)(stage * 16 * XS1 * 4);
        #pragma unroll
        for (int i = 0; i < 4; ++i) {
            int idx = tid + i * 512;
            int row = idx >> 7, c4 = idx & 127;
            CP_ASYNC16(dst0 + (uint32_t)((row * XS1 + c4 * 4) * 4),
                       xg + ((size_t)(b0 + row) * 512 + tt) * 512 + c4 * 4);
        }
        CP_COMMIT();
    };
    auto store_Y = [&](int tprev) {
        if (tid < 256) {
            const float* yb = ybuf + (tprev & 1) * 16 * 68;
            int row = tid >> 4, c4 = tid & 15;
            float4 v = *(const float4*)&yb[row * 68 + c4 * 4];
            int ttp = dir ? (511 - tprev) : tprev;
            size_t idx = ((size_t)(b0 + row) * 512 + ttp) * 256
                         + dir * 128 + rank * 64 + c4 * 4;
            __half h0,h1,h2,h3,l0,l1,l2,l3;
            split_h(v.x,h0,l0); split_h(v.y,h1,l1);
            split_h(v.z,h2,l2); split_h(v.w,h3,l3);
            *(uint2*)&Yhi[idx] = make_uint2(pack_h2(h0,h1), pack_h2(h2,h3));
            *(uint2*)&Ylo[idx] = make_uint2(pack_h2(l0,l1), pack_h2(l2,l3));
        }
    };

    __half* peer_h = (__half*)cl.map_shared_rank((void*)hbufh, rank ^ 1);
    __syncthreads();
    cl.sync();   // mbarrier init + hbuf zero visible cluster-wide

    issue_xg(dir ? 511 : 0, 0);
    issue_xg(dir ? 510 : 1, 1);
    CP_WAIT(1);  // stage 0 complete

    for (int t = 0; t < 512; ++t) {
        const int tt  = dir ? (511 - t) : t;
        const int cur = t & 1, nxt = cur ^ 1;

        // Single barrier per step: publishes xg stage t, step t-1's hbuf/ybuf,
        // and retires last iteration's xs reads.
        __syncthreads();

        if (t > 0) {
            if (tid == 0) {                     // release step t-1 stores to peer
                MBAR_ARRIVE_LOCAL(mbar);
                MBAR_ARRIVE_PEER(mbar, rank ^ 1);
            }
            store_Y(t - 1);                     // coalesced Y store of step t-1
        }
        if (t + 2 < 512) issue_xg(dir ? (509 - t) : (t + 2), (t + 2) % 3);

        // acc init = xg (needs only local smem)
        const float* xs = sxg + (t % 3) * 16 * XS1;
        float acc[2][4];
        #pragma unroll
        for (int nt = 0; nt < 2; ++nt) {
            acc[nt][0] = xs[r * XS1 + colA[nt]];
            acc[nt][1] = xs[r * XS1 + colA[nt] + 128];
            acc[nt][2] = xs[(r + 8) * XS1 + colA[nt]];
            acc[nt][3] = xs[(r + 8) * XS1 + colA[nt] + 128];
        }

        // wait for peer's step t-1 h before reading hbuf[cur]
        if (t > 0) MBAR_WAIT_CL(mbar, (t - 1) & 1);

        const uint32_t abase = hb32 + (uint32_t)(cur * 16 * HS1 * 2) + lmbase;
        #pragma unroll
        for (int kt = 0; kt < 8; ++kt) {
            uint32_t a0, a1, a2, a3;
            LDMATRIX_X4(a0, a1, a2, a3, abase + (uint32_t)(kt * 32));
            uint32_t afr[4] = {a0, a1, a2, a3};
            #pragma unroll
            for (int nt = 0; nt < 2; ++nt)
                mma_fp16(acc[nt], afr, bfr[nt][kt]);
        }

        float* yb = ybuf + (t & 1) * 16 * 68;
        #pragma unroll
        for (int nt = 0; nt < 2; ++nt) {
            float v0 = isState ? fmaxf(acc[nt][0], 0.f) : sigf(acc[nt][0]);
            float v1 = sigf(acc[nt][1]);
            float v2 = isState ? fmaxf(acc[nt][2], 0.f) : sigf(acc[nt][2]);
            float v3 = sigf(acc[nt][3]);
            float s0 = __shfl_xor_sync(0xffffffffu, v0, 1);
            float s1 = __shfl_xor_sync(0xffffffffu, v1, 1);
            float s2 = __shfl_xor_sync(0xffffffffu, v2, 1);
            float s3 = __shfl_xor_sync(0xffffffffu, v3, 1);
            if (isState) {
                float c0 = s1 * cst[nt][0] + s0 * v0;
                float c1 = s3 * cst[nt][1] + s2 * v2;
                cst[nt][0] = c0; cst[nt][1] = c1;
                float h0 = v1 * fmaxf(c0, 0.f);
                float h1 = v3 * fmaxf(c1, 0.f);
                __half h0h = __float2half(h0);
                __half h1h = __float2half(h1);
                int o0 = nxt * 16 * HS1 + r * HS1 + hj[nt];
                int o1 = nxt * 16 * HS1 + (r + 8) * HS1 + hj[nt];
                hbufh[o0] = h0h;  hbufh[o1] = h1h;
                peer_h[o0] = h0h; peer_h[o1] = h1h;
                yb[r * 68 + al[nt]]       = h0;
                yb[(r + 8) * 68 + al[nt]] = h1;
            }
        }

        if (t + 2 < 512) { CP_WAIT(1); }   // stage t+1 complete
        else             { CP_WAIT(0); }
    }

    // FIX (R11 ULF): keep this CTA alive until the peer's final-step DSMEM
    // writes into our hbuf have completed; also publishes ybuf for store_Y.
    __syncthreads();
    CLUSTER_ARRIVE();
    store_Y(511);              // global-only stores; overlap with cluster wait
    CLUSTER_WAIT();
}

// ------------- LSTM layer 2 (H=64) — fp16 recurrence, 512 threads -----------
#define XS2 260
#define HS2 72
__global__ void __launch_bounds__(512, 1)
lstm2_mma_kernel(const float* __restrict__ xg2f, const float* __restrict__ xg2b,
                 const float* __restrict__ r2f,  const float* __restrict__ r2b,
                 float* __restrict__ hout)
{
    extern __shared__ char smraw[];
    float*  sxg   = (float*)smraw;                     // 3*16*XS2 f32
    __half* hbufh = (__half*)(smraw + 3*16*XS2*4);     // 2*16*HS2 f16

    const int dir = blockIdx.y;
    const int b0  = blockIdx.x * 16;
    const int tid = threadIdx.x;
    const int lane = tid & 31, w = tid >> 5;           // 0..15
    const int q = lane & 3;
    const float* xg = dir ? xg2b : xg2f;
    const float* Wr = dir ? r2b : r2f;

    uint32_t bfr[2][4][2];
    #pragma unroll
    for (int nt = 0; nt < 2; ++nt) {
        int n_local = w * 16 + nt * 8 + (lane >> 2);
        int G = (n_local & 3) * 64 + (n_local >> 2);
        #pragma unroll
        for (int kt = 0; kt < 4; ++kt)
            #pragma unroll
            for (int p = 0; p < 2; ++p) {
                int k = kt * 16 + q * 2 + p * 8;
                bfr[nt][kt][p] = pack_h2(__float2half(Wr[k * 256 + G]),
                                         __float2half(Wr[(k + 1) * 256 + G]));
            }
    }

    for (int i = tid; i < 2 * 16 * HS2; i += 512) hbufh[i] = __float2half(0.f);

    const uint32_t hb32 = smem_u32(hbufh);
    const uint32_t xbase = smem_u32(sxg);
    const uint32_t lmbase = (uint32_t)(((lane & 15) * HS2 + ((lane >> 4) << 3)) * 2);
    const bool isState = (lane & 1);
    const int g0 = (q & 1) * 2;
    int colA[2], hj[2];
    #pragma unroll
    for (int nt = 0; nt < 2; ++nt) {
        int a_local = w * 4 + nt * 2 + (q >> 1);
        colA[nt] = g0 * 64 + a_local;
        hj[nt]   = a_local;
    }
    const int r = lane >> 2;

    float cst[2][2];
    #pragma unroll
    for (int nt = 0; nt < 2; ++nt) { cst[nt][0] = 0.f; cst[nt][1] = 0.f; }

    auto issue_xg = [&](int tt, int stage) {
        const uint32_t dst0 = xbase + (uint32_t)(stage * 16 * XS2 * 4);
        #pragma unroll
        for (int i = 0; i < 2; ++i) {
            int idx = tid + i * 512;
            int row = idx >> 6, c4 = idx & 63;
            CP_ASYNC16(dst0 + (uint32_t)((row * XS2 + c4 * 4) * 4),
                       xg + ((size_t)(b0 + row) * 512 + tt) * 256 + c4 * 4);
        }
        CP_COMMIT();
    };

    __syncthreads();
    issue_xg(dir ? 511 : 0, 0);
    issue_xg(dir ? 510 : 1, 1);
    CP_WAIT(1);

    for (int t = 0; t < 512; ++t) {
        const int tt  = dir ? (511 - t) : t;
        const int cur = t & 1, nxt = cur ^ 1;

        __syncthreads();   // single barrier per step

        if (t + 2 < 512) issue_xg(dir ? (509 - t) : (t + 2), (t + 2) % 3);

        const float* xs = sxg + (t % 3) * 16 * XS2;
        float acc[2][4];
        #pragma unroll
        for (int nt = 0; nt < 2; ++nt) {
            acc[nt][0] = xs[r * XS2 + colA[nt]];
            acc[nt][1] = xs[r * XS2 + colA[nt] + 64];
            acc[nt][2] = xs[(r + 8) * XS2 + colA[nt]];
            acc[nt][3] = xs[(r + 8) * XS2 + colA[nt] + 64];
        }

        const uint32_t abase = hb32 + (uint32_t)(cur * 16 * HS2 * 2) + lmbase;
        #pragma unroll
        for (int kt = 0; kt < 4; ++kt) {
            uint32_t a0, a1, a2, a3;
            LDMATRIX_X4(a0, a1, a2, a3, abase + (uint32_t)(kt * 32));
            uint32_t afr[4] = {a0, a1, a2, a3};
            #pragma unroll
            for (int nt = 0; nt < 2; ++nt)
                mma_fp16(acc[nt], afr, bfr[nt][kt]);
        }

        #pragma unroll
        for (int nt = 0; nt < 2; ++nt) {
            float v0 = isState ? fmaxf(acc[nt][0], 0.f) : sigf(acc[nt][0]);
            float v1 = sigf(acc[nt][1]);
            float v2 = isState ? fmaxf(acc[nt][2], 0.f) : sigf(acc[nt][2]);
            float v3 = sigf(acc[nt][3]);
            float s0 = __shfl_xor_sync(0xffffffffu, v0, 1);
            float s1 = __shfl_xor_sync(0xffffffffu, v1, 1);
            float s2 = __shfl_xor_sync(0xffffffffu, v2, 1);
            float s3 = __shfl_xor_sync(0xffffffffu, v3, 1);
            if (isState) {
                float c0 = s1 * cst[nt][0] + s0 * v0;
                float c1 = s3 * cst[nt][1] + s2 * v2;
                cst[nt][0] = c0; cst[nt][1] = c1;
                float h0 = v1 * fmaxf(c0, 0.f);
                float h1 = v3 * fmaxf(c1, 0.f);
                hbufh[nxt * 16 * HS2 + r * HS2 + hj[nt]]       = __float2half(h0);
                hbufh[nxt * 16 * HS2 + (r + 8) * HS2 + hj[nt]] = __float2half(h1);
                if (t == 511) {
                    hout[(size_t)(b0 + r) * 128 + dir * 64 + hj[nt]]     = h0;
                    hout[(size_t)(b0 + r + 8) * 128 + dir * 64 + hj[nt]] = h1;
                }
            }
        }

        if (t + 2 < 512) { CP_WAIT(1); }
        else             { CP_WAIT(0); }
    }
}

// ------------------------------ heads ---------------------------------------
__global__ void __launch_bounds__(256)
head_kernel(const float* __restrict__ x64, const float* __restrict__ h2,
            const float* __restrict__ wz1, const float* __restrict__ bz1,
            const float* __restrict__ wz2, const float* __restrict__ bz2,
            const float* __restrict__ wt1, const float* __restrict__ bt1,
            const float* __restrict__ wt2, const float* __restrict__ bt2,
            float* __restrict__ out)
{
    const int b = threadIdx.x;
    float comb[192];
    #pragma unroll 4
    for (int k = 0; k < 64; ++k)  comb[k]      = x64[b*64 + k];
    #pragma unroll 4
    for (int k = 0; k < 128; ++k) comb[64 + k] = h2[b*128 + k];

    float z0 = bz1[0], z1 = bz1[1], t0 = bt1[0], t1 = bt1[1];
    #pragma unroll 4
    for (int k = 0; k < 192; ++k) {
        float v = comb[k];
        z0 += v * wz1[k*2 + 0]; z1 += v * wz1[k*2 + 1];
        t0 += v * wt1[k*2 + 0]; t1 += v * wt1[k*2 + 1];
    }
    out[b]       = fmaxf(z0,0.f)*wz2[0] + fmaxf(z1,0.f)*wz2[1] + bz2[0];
    out[256 + b] = fmaxf(t0,0.f)*wt2[0] + fmaxf(t1,0.f)*wt2[1] + bt2[0];
}

// ------------------------------ launcher ------------------------------------
extern "C" void kernel_launch(void* const* d_in, const int* in_sizes, int n_in,
                              void* d_out, int out_size)
{
    const int*   inputA = (const int*)  d_in[0];
    const float* inputB = (const float*)d_in[1];
    const float* emb = (const float*)d_in[2];
    const float *w1=(const float*)d_in[3],  *b1=(const float*)d_in[4];
    const float *w2=(const float*)d_in[5],  *b2=(const float*)d_in[6];
    const float *w3=(const float*)d_in[7],  *b3=(const float*)d_in[8];
    const float *k1f=(const float*)d_in[9],  *r1f=(const float*)d_in[10], *bb1f=(const float*)d_in[11];
    const float *k1b=(const float*)d_in[12], *r1b=(const float*)d_in[13], *bb1b=(const float*)d_in[14];
    const float *k2f=(const float*)d_in[15], *r2f=(const float*)d_in[16], *bb2f=(const float*)d_in[17];
    const float *k2b=(const float*)d_in[18], *r2b=(const float*)d_in[19], *bb2b=(const float*)d_in[20];
    const float *wz1=(const float*)d_in[21], *bz1=(const float*)d_in[22];
    const float *wz2=(const float*)d_in[23], *bz2=(const float*)d_in[24];
    const float *wt1=(const float*)d_in[25], *bt1=(const float*)d_in[26];
    const float *wt2=(const float*)d_in[27], *bt2=(const float*)d_in[28];
    float* out = (float*)d_out;

    float *xg1f, *xg1b, *xg2f, *xg2b, *x64, *h2;
    __half *xBhi, *xBlo, *Yhi, *Ylo, *wTh;
    cudaGetSymbolAddress((void**)&xg1f, g_xg1f);
    cudaGetSymbolAddress((void**)&xg1b, g_xg1b);
    cudaGetSymbolAddress((void**)&xg2f, g_xg2f);
    cudaGetSymbolAddress((void**)&xg2b, g_xg2b);
    cudaGetSymbolAddress((void**)&x64,  g_x64);
    cudaGetSymbolAddress((void**)&h2,   g_h2);
    cudaGetSymbolAddress((void**)&xBhi, g_xBhi);
    cudaGetSymbolAddress((void**)&xBlo, g_xBlo);
    cudaGetSymbolAddress((void**)&Yhi,  g_Yhi);
    cudaGetSymbolAddress((void**)&Ylo,  g_Ylo);
    cudaGetSymbolAddress((void**)&wTh,  g_wTh);

    __half *w1fh = wTh,            *w1bh = wTh + 65536;
    __half *w2fh = wTh + 2*65536,  *w2bh = wTh + 3*65536;

    const size_t sm1 = (size_t)(3*16*XS1*4 + 2*16*HS1*2 + 2*16*68*4 + 16);
    const size_t sm2 = (size_t)(3*16*XS2*4 + 2*16*HS2*2);

    static bool attr_done = false;
    if (!attr_done) {
        cudaFuncSetAttribute(gemm_fp16_kernel, cudaFuncAttributeMaxDynamicSharedMemorySize, 2*GSTAGE);
        cudaFuncSetAttribute(lstm1_mma_kernel, cudaFuncAttributeMaxDynamicSharedMemorySize, (int)sm1);
        cudaFuncSetAttribute(lstm2_mma_kernel, cudaFuncAttributeMaxDynamicSharedMemorySize, (int)sm2);
        attr_done = true;
    }

    prep_kernel<<<(SPLIT_N4 + 4*65536 + 255)/256, 256>>>(inputB, xBhi, xBlo,
                                                         k1f, k1b, k2f, k2b, wTh);  // 0
    const size_t gsm = 2*GSTAGE;
    gemm_fp16_kernel<<<dim3(1024,4), 256, gsm>>>(xBhi, xBlo, w1fh, bb1f, xg1f, BT, 512, 128); // 1
    gemm_fp16_kernel<<<dim3(1024,4), 256, gsm>>>(xBhi, xBlo, w1bh, bb1b, xg1b, BT, 512, 128); // 2

    lstm1_mma_kernel<<<dim3(32,2), 512, sm1>>>(xg1f, xg1b, r1f, r1b, Yhi, Ylo);     // 3

    gemm_fp16_kernel<<<dim3(1024,2), 256, gsm>>>(Yhi, Ylo, w2fh, bb2f, xg2f, BT, 256, 256);   // 4
    gemm_fp16_kernel<<<dim3(1024,2), 256, gsm>>>(Yhi, Ylo, w2bh, bb2b, xg2b, BT, 256, 256);   // 5

    lstm2_mma_kernel<<<dim3(16,2), 512, sm2>>>(xg2f, xg2b, r2f, r2b, h2);           // 6

    emb_mlp_kernel<<<256, 256>>>(inputA, emb, w1,b1, w2,b2, w3,b3, x64);            // 7
    head_kernel<<<1, 256>>>(x64, h2, wz1,bz1, wz2,bz2, wt1,bt1, wt2,bt2, out);      // 8
}